// round 12
// baseline (speedup 1.0000x reference)
#include <cuda_runtime.h>
#include <cuda_fp16.h>
#include <math.h>
#include <stdint.h>

// Problem shape (fixed by the dataset)
#define NB      4
#define SEQ     4096
#define DDIM    1024
#define HDIM    128
#define BSTOT   (NB * SEQ)          // 16384 rows
#define NQT     64                  // q-tiles per batch (SEQ/64)

// ---------------- scratch (no cudaMalloc allowed) ----------------
__device__ __half g_Wh[3 * DDIM * HDIM];    // fp16 Wq|Wk|Wv
__device__ __half g_Qh[BSTOT * HDIM];       // fp16 Q (pre-scaled by log2e/sqrt(128))
__device__ __half g_Kh[BSTOT * HDIM];
__device__ __half g_Vh[BSTOT * HDIM];
// split-K partials: [b][qtile][half]{ o:64x128, m:64, l:64 }  (m in log2 domain)
__device__ float g_Po[NB * NQT * 2 * 64 * HDIM];
__device__ float g_Pm[NB * NQT * 2 * 64];
__device__ float g_Pl[NB * NQT * 2 * 64];
__device__ int   g_flags[NB * NQT];         // split-K arrival counters (memset per call)

// ------------------- helpers -------------------
// fp16: D += A(16x16, row) * B(16x8, col), fp32 accum
__device__ __forceinline__ void mma16(float* c, const uint32_t* a, const uint32_t* b) {
    asm volatile("mma.sync.aligned.m16n8k16.row.col.f32.f16.f16.f32 "
        "{%0,%1,%2,%3}, {%4,%5,%6,%7}, {%8,%9}, {%0,%1,%2,%3};"
        : "+f"(c[0]), "+f"(c[1]), "+f"(c[2]), "+f"(c[3])
        : "r"(a[0]), "r"(a[1]), "r"(a[2]), "r"(a[3]), "r"(b[0]), "r"(b[1]));
}
__device__ __forceinline__ void ldsm4(uint32_t& r0, uint32_t& r1, uint32_t& r2, uint32_t& r3,
                                      uint32_t addr) {
    asm volatile("ldmatrix.sync.aligned.m8n8.x4.shared.b16 {%0,%1,%2,%3}, [%4];"
        : "=r"(r0), "=r"(r1), "=r"(r2), "=r"(r3) : "r"(addr));
}
__device__ __forceinline__ void ldsm4t(uint32_t& r0, uint32_t& r1, uint32_t& r2, uint32_t& r3,
                                       uint32_t addr) {
    asm volatile("ldmatrix.sync.aligned.m8n8.x4.trans.shared.b16 {%0,%1,%2,%3}, [%4];"
        : "=r"(r0), "=r"(r1), "=r"(r2), "=r"(r3) : "r"(addr));
}
// pack two f32 -> f16x2 (lo = first element)
__device__ __forceinline__ uint32_t ph2(float lo, float hi) {
    uint32_t r; asm("cvt.rn.f16x2.f32 %0, %1, %2;" : "=r"(r) : "f"(hi), "f"(lo)); return r;
}
// 2^x, single MUFU op (exp done in log2 domain)
__device__ __forceinline__ float ex2(float x) {
    float r; asm("ex2.approx.ftz.f32 %0, %1;" : "=f"(r) : "f"(x)); return r;
}
__device__ __forceinline__ uint32_t smaddr(const void* p) {
    return (uint32_t)__cvta_generic_to_shared(p);
}
__device__ __forceinline__ void cp16(uint32_t s, const void* g) {
    asm volatile("cp.async.ca.shared.global [%0], [%1], 16;" :: "r"(s), "l"(g));
}
__device__ __forceinline__ void cp_commit() {
    asm volatile("cp.async.commit_group;");
}
template <int N>
__device__ __forceinline__ void cp_wait() {
    asm volatile("cp.async.wait_group %0;" :: "n"(N));
}

// ======================= W fp32 -> fp16 =========================
__global__ __launch_bounds__(256) void convert_W_kernel(
    const float* __restrict__ Wq, const float* __restrict__ Wk,
    const float* __restrict__ Wv)
{
    const float* W = (blockIdx.y == 0) ? Wq : ((blockIdx.y == 1) ? Wk : Wv);
    size_t i = ((size_t)blockIdx.x * 256 + threadIdx.x) * 8;
    float4 a = *(const float4*)(W + i);
    float4 b = *(const float4*)(W + i + 4);
    uint4 o;
    o.x = ph2(a.x, a.y); o.y = ph2(a.z, a.w);
    o.z = ph2(b.x, b.y); o.w = ph2(b.z, b.w);
    *(uint4*)(g_Wh + (size_t)blockIdx.y * DDIM * HDIM + i) = o;
}

// ======================= fused QKV projection =========================
// [Q|K|V][64 rows, 384 cols] = X[64,1024] (fp32, converted in-kernel) @ Wh[1024,384].
// 512 thr = 16 warps: wm=warp&3 (16 rows), wn=warp>>2 (96 cols = 12 n-tiles).
#define FXS 40    // X fp16 smem stride (halves)
#define FWS 392   // W fp16 smem stride (halves)
#define FUSED_SMEM ((2 * 64 * FXS + 2 * 32 * FWS) * 2)   // 60416 B

__global__ __launch_bounds__(512) void fused_proj_kernel(const float* __restrict__ X)
{
    extern __shared__ __half fsm[];
    __half* Xb = fsm;                    // [2][64*FXS]
    __half* Wb = fsm + 2 * 64 * FXS;     // [2][32*FWS]

    const int tid  = threadIdx.x;
    const int warp = tid >> 5, lane = tid & 31;
    const int g = lane >> 2, tig = lane & 3;
    const int wm = warp & 3;      // 4 M-groups x 16 rows
    const int wn = warp >> 2;     // 4 N-groups x 96 cols
    const int row0 = blockIdx.x * 64;

    auto issue_W = [&](int k0, int s) {
        __half* Wd = Wb + s * 32 * FWS;
#pragma unroll
        for (int c = tid; c < 1536; c += 512) {     // 32 rows x 48 chunks of 8 halves
            int r = c / 48, cc = c % 48;
            int mat = cc >> 4, col = (cc & 15) * 8;
            cp16(smaddr(Wd + r * FWS + cc * 8),
                 g_Wh + (size_t)mat * DDIM * HDIM + (size_t)(k0 + r) * HDIM + col);
        }
        cp_commit();
    };

    const int xr = tid >> 3, xc = (tid & 7) * 4;

    float acc[12][4];
#pragma unroll
    for (int nt = 0; nt < 12; nt++)
#pragma unroll
        for (int j = 0; j < 4; j++) acc[nt][j] = 0.f;

    float4 xreg = *(const float4*)(X + (size_t)(row0 + xr) * DDIM + xc);
    issue_W(0, 0);

    const int a_off = (lane & 15) * FXS + (lane >> 4) * 8;
    const int b_off = lane * FWS;

    for (int ki = 0; ki < 32; ki++) {
        {   // store prefetched X tile (cvt fp32->fp16) into buf ki&1
            uint2 p; p.x = ph2(xreg.x, xreg.y); p.y = ph2(xreg.z, xreg.w);
            *(uint2*)(Xb + (ki & 1) * 64 * FXS + xr * FXS + xc) = p;
        }
        if (ki < 31) {
            xreg = *(const float4*)(X + (size_t)(row0 + xr) * DDIM + (ki + 1) * 32 + xc);
            issue_W((ki + 1) * 32, (ki + 1) & 1);
            cp_wait<1>();
        } else {
            cp_wait<0>();
        }
        __syncthreads();

        const uint32_t XsA = smaddr(Xb + (ki & 1) * 64 * FXS);
        const uint32_t WsA = smaddr(Wb + (ki & 1) * 32 * FWS);

        uint32_t a0[4], a1[4];
        ldsm4(a0[0], a0[1], a0[2], a0[3], XsA + (uint32_t)(wm * 16 * FXS + a_off) * 2);
        ldsm4(a1[0], a1[1], a1[2], a1[3], XsA + (uint32_t)(wm * 16 * FXS + a_off + 16) * 2);
#pragma unroll
        for (int nt = 0; nt < 12; nt++) {
            uint32_t r0, r1, r2, r3;
            ldsm4t(r0, r1, r2, r3, WsA + (uint32_t)(b_off + wn * 96 + nt * 8) * 2);
            uint32_t b01[2] = {r0, r1}, b23[2] = {r2, r3};
            mma16(acc[nt], a0, b01);
            mma16(acc[nt], a1, b23);
        }
        __syncthreads();
    }

    // epilogue: route each n-tile to Q/K/V; Q pre-scaled into log2 domain
    const float qsc = 0.088388347648318447f * 1.4426950408889634f;
    const int r = row0 + wm * 16 + g;
#pragma unroll
    for (int nt = 0; nt < 12; nt++) {
        const int ncol = wn * 96 + nt * 8 + 2 * tig;
        const int mat = ncol >> 7, col = ncol & 127;
        __half* Outh = (mat == 0) ? g_Qh : ((mat == 1) ? g_Kh : g_Vh);
        const float sc = (mat == 0) ? qsc : 1.0f;
        *(uint32_t*)(Outh + (size_t)r       * HDIM + col) = ph2(acc[nt][0] * sc, acc[nt][1] * sc);
        *(uint32_t*)(Outh + (size_t)(r + 8) * HDIM + col) = ph2(acc[nt][2] * sc, acc[nt][3] * sc);
    }
}

// ======================= flash attention (split-K, fused merge) ===========
// grid (128, NB): bx -> qtile = 63-(bx>>1), half = bx&1.
// Q in regs, K+V joint double-buffered stages, 2-deep prefetch, log2 softmax.
// Last-arriving CTA of each qtile pair performs the combine and writes O.
#define HS 136                       // half-stride per smem row (272 B)
#define ATT_SMEM (4 * 64 * HS * 2)   // 2 K bufs + 2 V bufs = 69632 B

__global__ __launch_bounds__(128, 3) void attn_kernel(float* __restrict__ Out)
{
    extern __shared__ __half hsm[];
    __half* Kb = hsm;                  // [2][64*HS]
    __half* Vb = hsm + 2 * 64 * HS;    // [2][64*HS]

    const int tid  = threadIdx.x;
    const int warp = tid >> 5, lane = tid & 31;
    const int g = lane >> 2, tig = lane & 3;
    const int rb = warp * 16;
    const int b  = blockIdx.y;

    const __half* Q = g_Qh + (size_t)b * SEQ * HDIM;
    const __half* K = g_Kh + (size_t)b * SEQ * HDIM;
    const __half* V = g_Vh + (size_t)b * SEQ * HDIM;

    const int qtile = 63 - ((int)blockIdx.x >> 1);   // longest first
    const int half  = (int)blockIdx.x & 1;
    const int qbase = qtile * 64;
    const int n  = qtile + 1;
    const int n0 = (n + 1) >> 1;
    const int kt0 = half ? n0 : 0;
    const int kt1 = half ? n  : n0;

    auto issue_stage = [&](int kbase, int s) {
        __half* Kd = Kb + s * 64 * HS;
        __half* Vd = Vb + s * 64 * HS;
#pragma unroll
        for (int c = tid; c < 1024; c += 128) {
            int r = c >> 4, c8 = c & 15;
            cp16(smaddr(Kd + r * HS + c8 * 8),
                 K + (size_t)(kbase + r) * HDIM + c8 * 8);
            cp16(smaddr(Vd + r * HS + c8 * 8),
                 V + (size_t)(kbase + r) * HDIM + c8 * 8);
        }
        cp_commit();
    };

    float o[16][4];
#pragma unroll
    for (int nt = 0; nt < 16; nt++)
#pragma unroll
        for (int j = 0; j < 4; j++) o[nt][j] = 0.f;
    float mr[2] = {-INFINITY, -INFINITY};
    float lr[2] = {0.f, 0.f};

    if (kt0 < kt1) {
        // Q -> register A-fragments (fp16, log2-prescaled in gmem)
        uint32_t qa[8][4];
#pragma unroll
        for (int ks = 0; ks < 8; ks++) {
            const __half* q0 = Q + (size_t)(qbase + rb + g)     * HDIM + ks * 16;
            const __half* q1 = Q + (size_t)(qbase + rb + g + 8) * HDIM + ks * 16;
            qa[ks][0] = *(const uint32_t*)(q0 + 2 * tig);
            qa[ks][1] = *(const uint32_t*)(q1 + 2 * tig);
            qa[ks][2] = *(const uint32_t*)(q0 + 2 * tig + 8);
            qa[ks][3] = *(const uint32_t*)(q1 + 2 * tig + 8);
        }

        // ldmatrix per-thread offsets (in halves)
        const int kq_off = (lane & 7) * HS + (lane >> 3) * 8;
        const int vv_off = lane * HS;

        // prologue: 2-deep prefetch
        issue_stage(kt0 * 64, kt0 & 1);
        if (kt0 + 1 < kt1) issue_stage((kt0 + 1) * 64, (kt0 + 1) & 1);
        else               cp_commit();

        for (int kt = kt0; kt < kt1; kt++) {
            cp_wait<1>();          // stage kt arrived
            __syncthreads();

            const uint32_t KsA = smaddr(Kb + (kt & 1) * 64 * HS);
            const uint32_t VsA = smaddr(Vb + (kt & 1) * 64 * HS);

            // -------- S = Q K^T  (16x64 per warp; log2-domain scores) --------
            float s[8][4];
#pragma unroll
            for (int ni = 0; ni < 8; ni++)
#pragma unroll
                for (int j = 0; j < 4; j++) s[ni][j] = 0.f;

#pragma unroll
            for (int ni = 0; ni < 8; ni++) {
                const uint32_t base = KsA + (uint32_t)(ni * 8 * HS + kq_off) * 2;
#pragma unroll
                for (int kc = 0; kc < 4; kc++) {
                    uint32_t r0, r1, r2, r3;
                    ldsm4(r0, r1, r2, r3, base + kc * 64);
                    uint32_t b01[2] = {r0, r1}, b23[2] = {r2, r3};
                    mma16(s[ni], qa[2 * kc],     b01);
                    mma16(s[ni], qa[2 * kc + 1], b23);
                }
            }

            // -------- causal mask (diagonal tile only) --------
            if (kt == qtile) {
                const int r0l = rb + g, r1l = rb + g + 8;
#pragma unroll
                for (int ni = 0; ni < 8; ni++) {
                    const int c = ni * 8 + 2 * tig;
                    s[ni][0] = (c     <= r0l) ? s[ni][0] : -INFINITY;
                    s[ni][1] = (c + 1 <= r0l) ? s[ni][1] : -INFINITY;
                    s[ni][2] = (c     <= r1l) ? s[ni][2] : -INFINITY;
                    s[ni][3] = (c + 1 <= r1l) ? s[ni][3] : -INFINITY;
                }
            }

            // -------- online softmax (log2 domain, single EX2 per element) ----
#pragma unroll
            for (int h = 0; h < 2; h++) {
                float tm = -INFINITY;
#pragma unroll
                for (int ni = 0; ni < 8; ni++)
                    tm = fmaxf(tm, fmaxf(s[ni][2 * h], s[ni][2 * h + 1]));
                tm = fmaxf(tm, __shfl_xor_sync(0xffffffffu, tm, 1));
                tm = fmaxf(tm, __shfl_xor_sync(0xffffffffu, tm, 2));

                const float mn = fmaxf(mr[h], tm);
                const float alpha = ex2(mr[h] - mn);
                mr[h] = mn;

                float rs = 0.f;
#pragma unroll
                for (int ni = 0; ni < 8; ni++) {
                    float p0 = ex2(s[ni][2 * h]     - mn);
                    float p1 = ex2(s[ni][2 * h + 1] - mn);
                    s[ni][2 * h] = p0; s[ni][2 * h + 1] = p1;
                    rs += p0 + p1;
                }
                rs += __shfl_xor_sync(0xffffffffu, rs, 1);
                rs += __shfl_xor_sync(0xffffffffu, rs, 2);
                lr[h] = lr[h] * alpha + rs;

#pragma unroll
                for (int nt = 0; nt < 16; nt++) {
                    o[nt][2 * h]     *= alpha;
                    o[nt][2 * h + 1] *= alpha;
                }
            }

            // -------- P -> fp16 A-fragments --------
            uint32_t pa[4][4];
#pragma unroll
            for (int js = 0; js < 4; js++) {
                pa[js][0] = ph2(s[2 * js][0],     s[2 * js][1]);
                pa[js][1] = ph2(s[2 * js][2],     s[2 * js][3]);
                pa[js][2] = ph2(s[2 * js + 1][0], s[2 * js + 1][1]);
                pa[js][3] = ph2(s[2 * js + 1][2], s[2 * js + 1][3]);
            }

            // -------- O += P V  (16x128 per warp) --------
#pragma unroll
            for (int nt = 0; nt < 16; nt++) {
                const uint32_t base = VsA + (uint32_t)(vv_off + nt * 8) * 2;
#pragma unroll
                for (int kc = 0; kc < 2; kc++) {
                    uint32_t r0, r1, r2, r3;
                    ldsm4t(r0, r1, r2, r3, base + kc * (32 * HS * 2));
                    uint32_t b01[2] = {r0, r1}, b23[2] = {r2, r3};
                    mma16(o[nt], pa[2 * kc],     b01);
                    mma16(o[nt], pa[2 * kc + 1], b23);
                }
            }

            // -------- all warps done reading stage kt; refill its buffer ------
            __syncthreads();
            if (kt + 2 < kt1) issue_stage((kt + 2) * 64, kt & 1);
            else              cp_commit();    // keep wait<1> invariant exact
        }

        cp_wait<0>();
    }

    // -------- epilogue: publish partial (o, m, l); m in log2 domain --------
    const int fq = b * NQT + qtile;
    const size_t pidx = (size_t)fq * 2 + half;
    float* Po = g_Po + pidx * (64 * HDIM);
#pragma unroll
    for (int nt = 0; nt < 16; nt++) {
        const int c = nt * 8 + 2 * tig;
        *(float2*)(Po + (rb + g)     * HDIM + c) = make_float2(o[nt][0], o[nt][1]);
        *(float2*)(Po + (rb + g + 8) * HDIM + c) = make_float2(o[nt][2], o[nt][3]);
    }
    if (tig == 0) {
        g_Pm[pidx * 64 + rb + g]     = mr[0];
        g_Pm[pidx * 64 + rb + g + 8] = mr[1];
        g_Pl[pidx * 64 + rb + g]     = lr[0];
        g_Pl[pidx * 64 + rb + g + 8] = lr[1];
    }

    // -------- last-arriver merges this qtile (deterministic combine) --------
    __threadfence();
    __syncthreads();
    int* sflag = (int*)hsm;
    if (tid == 0) sflag[0] = atomicAdd(&g_flags[fq], 1);
    __syncthreads();
    if (sflag[0] == 1) {
        __threadfence();
        float* wsm = (float*)hsm + 8;   // [2][64] combine weights
        const size_t base = (size_t)fq * 2;
        if (tid < 64) {
            float m0 = __ldcg(g_Pm + base * 64 + tid);
            float m1 = __ldcg(g_Pm + (base + 1) * 64 + tid);
            float l0 = __ldcg(g_Pl + base * 64 + tid);
            float l1 = __ldcg(g_Pl + (base + 1) * 64 + tid);
            float M  = fmaxf(m0, m1);
            float w0 = ex2(m0 - M), w1 = ex2(m1 - M);
            float invL = 1.0f / (l0 * w0 + l1 * w1);
            wsm[tid]      = w0 * invL;
            wsm[64 + tid] = w1 * invL;
        }
        __syncthreads();
        const float* o0 = g_Po + base * (64 * HDIM);
        const float* o1 = o0 + 64 * HDIM;
        float* O = Out + (size_t)b * SEQ * HDIM + (size_t)qbase * HDIM;
        for (int idx = tid; idx < 2048; idx += 128) {
            int r = idx >> 5, c4 = (idx & 31) * 4;
            float4 a  = __ldcg((const float4*)(o0 + r * HDIM + c4));
            float4 bb = __ldcg((const float4*)(o1 + r * HDIM + c4));
            const float W0 = wsm[r], W1 = wsm[64 + r];
            float4 res;
            res.x = a.x * W0 + bb.x * W1;
            res.y = a.y * W0 + bb.y * W1;
            res.z = a.z * W0 + bb.z * W1;
            res.w = a.w * W0 + bb.w * W1;
            *(float4*)(O + r * HDIM + c4) = res;
        }
    }
}

// =========================== launch =============================
extern "C" void kernel_launch(void* const* d_in, const int* in_sizes, int n_in,
                              void* d_out, int out_size)
{
    (void)in_sizes; (void)n_in; (void)out_size;
    const float* X  = (const float*)d_in[0];
    const float* Wq = (const float*)d_in[1];
    const float* Wk = (const float*)d_in[2];
    const float* Wv = (const float*)d_in[3];
    float* Out = (float*)d_out;

    static void* flags_ptr = nullptr;
    static int attr_set = 0;
    if (!attr_set) {
        cudaFuncSetAttribute(fused_proj_kernel,
                             cudaFuncAttributeMaxDynamicSharedMemorySize,
                             FUSED_SMEM);
        cudaFuncSetAttribute(attn_kernel,
                             cudaFuncAttributeMaxDynamicSharedMemorySize,
                             ATT_SMEM);
        cudaGetSymbolAddress(&flags_ptr, g_flags);
        attr_set = 1;
    }

    // zero split-K flags (graph-capturable memset node)
    cudaMemsetAsync(flags_ptr, 0, NB * NQT * sizeof(int));

    // W fp32 -> fp16 (concat layout)
    dim3 wgrid(DDIM * HDIM / (256 * 8), 3);
    convert_W_kernel<<<wgrid, 256>>>(Wq, Wk, Wv);

    // Fused QKV projection (reads fp32 X once)
    fused_proj_kernel<<<BSTOT / 64, 512, FUSED_SMEM>>>(X);

    // Flash attention, split-K halves, fused merge
    dim3 agrid(128, NB);
    attn_kernel<<<agrid, 128, ATT_SMEM>>>(Out);
}

// round 13
// speedup vs baseline: 1.0581x; 1.0581x over previous
#include <cuda_runtime.h>
#include <cuda_fp16.h>
#include <math.h>
#include <stdint.h>

// Problem shape (fixed by the dataset)
#define NB      4
#define SEQ     4096
#define DDIM    1024
#define HDIM    128
#define BSTOT   (NB * SEQ)          // 16384 rows
#define NQT     64                  // q-tiles per batch (SEQ/64)

// ---------------- scratch (no cudaMalloc allowed) ----------------
__device__ __half g_Wh[3 * DDIM * HDIM];    // fp16 Wq|Wk|Wv
__device__ __half g_Qh[BSTOT * HDIM];       // fp16 Q (pre-scaled by log2e/sqrt(128))
__device__ __half g_Kh[BSTOT * HDIM];
__device__ __half g_Vh[BSTOT * HDIM];
// split-K partials: [b][qtile][half]{ o:64x128, m:64, l:64 }  (m in log2 domain)
__device__ float g_Po[NB * NQT * 2 * 64 * HDIM];
__device__ float g_Pm[NB * NQT * 2 * 64];
__device__ float g_Pl[NB * NQT * 2 * 64];

// ------------------- helpers -------------------
// fp16: D += A(16x16, row) * B(16x8, col), fp32 accum
__device__ __forceinline__ void mma16(float* c, const uint32_t* a, const uint32_t* b) {
    asm volatile("mma.sync.aligned.m16n8k16.row.col.f32.f16.f16.f32 "
        "{%0,%1,%2,%3}, {%4,%5,%6,%7}, {%8,%9}, {%0,%1,%2,%3};"
        : "+f"(c[0]), "+f"(c[1]), "+f"(c[2]), "+f"(c[3])
        : "r"(a[0]), "r"(a[1]), "r"(a[2]), "r"(a[3]), "r"(b[0]), "r"(b[1]));
}
__device__ __forceinline__ void ldsm4(uint32_t& r0, uint32_t& r1, uint32_t& r2, uint32_t& r3,
                                      uint32_t addr) {
    asm volatile("ldmatrix.sync.aligned.m8n8.x4.shared.b16 {%0,%1,%2,%3}, [%4];"
        : "=r"(r0), "=r"(r1), "=r"(r2), "=r"(r3) : "r"(addr));
}
__device__ __forceinline__ void ldsm4t(uint32_t& r0, uint32_t& r1, uint32_t& r2, uint32_t& r3,
                                       uint32_t addr) {
    asm volatile("ldmatrix.sync.aligned.m8n8.x4.trans.shared.b16 {%0,%1,%2,%3}, [%4];"
        : "=r"(r0), "=r"(r1), "=r"(r2), "=r"(r3) : "r"(addr));
}
// pack two f32 -> f16x2 (lo = first element)
__device__ __forceinline__ uint32_t ph2(float lo, float hi) {
    uint32_t r; asm("cvt.rn.f16x2.f32 %0, %1, %2;" : "=r"(r) : "f"(hi), "f"(lo)); return r;
}
// 2^x, single MUFU op (exp done in log2 domain)
__device__ __forceinline__ float ex2(float x) {
    float r; asm("ex2.approx.ftz.f32 %0, %1;" : "=f"(r) : "f"(x)); return r;
}
__device__ __forceinline__ uint32_t smaddr(const void* p) {
    return (uint32_t)__cvta_generic_to_shared(p);
}
__device__ __forceinline__ void cp16(uint32_t s, const void* g) {
    asm volatile("cp.async.ca.shared.global [%0], [%1], 16;" :: "r"(s), "l"(g));
}
__device__ __forceinline__ void cp_commit() {
    asm volatile("cp.async.commit_group;");
}
template <int N>
__device__ __forceinline__ void cp_wait() {
    asm volatile("cp.async.wait_group %0;" :: "n"(N));
}

// ======================= W fp32 -> fp16 =========================
__global__ __launch_bounds__(256) void convert_W_kernel(
    const float* __restrict__ Wq, const float* __restrict__ Wk,
    const float* __restrict__ Wv)
{
    const float* W = (blockIdx.y == 0) ? Wq : ((blockIdx.y == 1) ? Wk : Wv);
    size_t i = ((size_t)blockIdx.x * 256 + threadIdx.x) * 8;
    float4 a = *(const float4*)(W + i);
    float4 b = *(const float4*)(W + i + 4);
    uint4 o;
    o.x = ph2(a.x, a.y); o.y = ph2(a.z, a.w);
    o.z = ph2(b.x, b.y); o.w = ph2(b.z, b.w);
    *(uint4*)(g_Wh + (size_t)blockIdx.y * DDIM * HDIM + i) = o;
}

// ======================= fused QKV projection =========================
// [Q|K|V][64 rows, 384 cols] = X[64,1024] (fp32, converted in-kernel) @ Wh[1024,384].
// 512 thr = 16 warps: wm=warp&3 (16 rows), wn=warp>>2 (96 cols = 12 n-tiles).
#define FXS 40    // X fp16 smem stride (halves)
#define FWS 392   // W fp16 smem stride (halves)
#define FUSED_SMEM ((2 * 64 * FXS + 2 * 32 * FWS) * 2)   // 60416 B

__global__ __launch_bounds__(512) void fused_proj_kernel(const float* __restrict__ X)
{
    extern __shared__ __half fsm[];
    __half* Xb = fsm;                    // [2][64*FXS]
    __half* Wb = fsm + 2 * 64 * FXS;     // [2][32*FWS]

    const int tid  = threadIdx.x;
    const int warp = tid >> 5, lane = tid & 31;
    const int g = lane >> 2, tig = lane & 3;
    const int wm = warp & 3;      // 4 M-groups x 16 rows
    const int wn = warp >> 2;     // 4 N-groups x 96 cols
    const int row0 = blockIdx.x * 64;

    auto issue_W = [&](int k0, int s) {
        __half* Wd = Wb + s * 32 * FWS;
#pragma unroll
        for (int c = tid; c < 1536; c += 512) {     // 32 rows x 48 chunks of 8 halves
            int r = c / 48, cc = c % 48;
            int mat = cc >> 4, col = (cc & 15) * 8;
            cp16(smaddr(Wd + r * FWS + cc * 8),
                 g_Wh + (size_t)mat * DDIM * HDIM + (size_t)(k0 + r) * HDIM + col);
        }
        cp_commit();
    };

    const int xr = tid >> 3, xc = (tid & 7) * 4;

    float acc[12][4];
#pragma unroll
    for (int nt = 0; nt < 12; nt++)
#pragma unroll
        for (int j = 0; j < 4; j++) acc[nt][j] = 0.f;

    float4 xreg = *(const float4*)(X + (size_t)(row0 + xr) * DDIM + xc);
    issue_W(0, 0);

    const int a_off = (lane & 15) * FXS + (lane >> 4) * 8;
    const int b_off = lane * FWS;

    for (int ki = 0; ki < 32; ki++) {
        {   // store prefetched X tile (cvt fp32->fp16) into buf ki&1
            uint2 p; p.x = ph2(xreg.x, xreg.y); p.y = ph2(xreg.z, xreg.w);
            *(uint2*)(Xb + (ki & 1) * 64 * FXS + xr * FXS + xc) = p;
        }
        if (ki < 31) {
            xreg = *(const float4*)(X + (size_t)(row0 + xr) * DDIM + (ki + 1) * 32 + xc);
            issue_W((ki + 1) * 32, (ki + 1) & 1);
            cp_wait<1>();
        } else {
            cp_wait<0>();
        }
        __syncthreads();

        const uint32_t XsA = smaddr(Xb + (ki & 1) * 64 * FXS);
        const uint32_t WsA = smaddr(Wb + (ki & 1) * 32 * FWS);

        uint32_t a0[4], a1[4];
        ldsm4(a0[0], a0[1], a0[2], a0[3], XsA + (uint32_t)(wm * 16 * FXS + a_off) * 2);
        ldsm4(a1[0], a1[1], a1[2], a1[3], XsA + (uint32_t)(wm * 16 * FXS + a_off + 16) * 2);
#pragma unroll
        for (int nt = 0; nt < 12; nt++) {
            uint32_t r0, r1, r2, r3;
            ldsm4t(r0, r1, r2, r3, WsA + (uint32_t)(b_off + wn * 96 + nt * 8) * 2);
            uint32_t b01[2] = {r0, r1}, b23[2] = {r2, r3};
            mma16(acc[nt], a0, b01);
            mma16(acc[nt], a1, b23);
        }
        __syncthreads();
    }

    // epilogue: route each n-tile to Q/K/V; Q pre-scaled into log2 domain
    const float qsc = 0.088388347648318447f * 1.4426950408889634f;
    const int r = row0 + wm * 16 + g;
#pragma unroll
    for (int nt = 0; nt < 12; nt++) {
        const int ncol = wn * 96 + nt * 8 + 2 * tig;
        const int mat = ncol >> 7, col = ncol & 127;
        __half* Outh = (mat == 0) ? g_Qh : ((mat == 1) ? g_Kh : g_Vh);
        const float sc = (mat == 0) ? qsc : 1.0f;
        *(uint32_t*)(Outh + (size_t)r       * HDIM + col) = ph2(acc[nt][0] * sc, acc[nt][1] * sc);
        *(uint32_t*)(Outh + (size_t)(r + 8) * HDIM + col) = ph2(acc[nt][2] * sc, acc[nt][3] * sc);
    }
}

// ======================= flash attention (split-K) ========================
// grid (128, NB): bx -> qtile = 63-(bx>>1), half = bx&1.
// Q in regs, K+V joint double-buffered stages, 2-deep prefetch;
// launch_bounds(128,3) for 3 CTAs/SM; softmax in log2 domain (single EX2).
#define HS 136                       // half-stride per smem row (272 B)
#define ATT_SMEM (4 * 64 * HS * 2)   // 2 K bufs + 2 V bufs = 69632 B

__global__ __launch_bounds__(128, 3) void attn_kernel()
{
    extern __shared__ __half hsm[];
    __half* Kb = hsm;                  // [2][64*HS]
    __half* Vb = hsm + 2 * 64 * HS;    // [2][64*HS]

    const int tid  = threadIdx.x;
    const int warp = tid >> 5, lane = tid & 31;
    const int g = lane >> 2, tig = lane & 3;
    const int rb = warp * 16;
    const int b  = blockIdx.y;

    const __half* Q = g_Qh + (size_t)b * SEQ * HDIM;
    const __half* K = g_Kh + (size_t)b * SEQ * HDIM;
    const __half* V = g_Vh + (size_t)b * SEQ * HDIM;

    const int qtile = 63 - ((int)blockIdx.x >> 1);   // longest first
    const int half  = (int)blockIdx.x & 1;
    const int qbase = qtile * 64;
    const int n  = qtile + 1;
    const int n0 = (n + 1) >> 1;
    const int kt0 = half ? n0 : 0;
    const int kt1 = half ? n  : n0;

    auto issue_stage = [&](int kbase, int s) {
        __half* Kd = Kb + s * 64 * HS;
        __half* Vd = Vb + s * 64 * HS;
#pragma unroll
        for (int c = tid; c < 1024; c += 128) {
            int r = c >> 4, c8 = c & 15;
            cp16(smaddr(Kd + r * HS + c8 * 8),
                 K + (size_t)(kbase + r) * HDIM + c8 * 8);
            cp16(smaddr(Vd + r * HS + c8 * 8),
                 V + (size_t)(kbase + r) * HDIM + c8 * 8);
        }
        cp_commit();
    };

    float o[16][4];
#pragma unroll
    for (int nt = 0; nt < 16; nt++)
#pragma unroll
        for (int j = 0; j < 4; j++) o[nt][j] = 0.f;
    float mr[2] = {-INFINITY, -INFINITY};
    float lr[2] = {0.f, 0.f};

    if (kt0 < kt1) {
        // Q -> register A-fragments (fp16, log2-prescaled in gmem)
        uint32_t qa[8][4];
#pragma unroll
        for (int ks = 0; ks < 8; ks++) {
            const __half* q0 = Q + (size_t)(qbase + rb + g)     * HDIM + ks * 16;
            const __half* q1 = Q + (size_t)(qbase + rb + g + 8) * HDIM + ks * 16;
            qa[ks][0] = *(const uint32_t*)(q0 + 2 * tig);
            qa[ks][1] = *(const uint32_t*)(q1 + 2 * tig);
            qa[ks][2] = *(const uint32_t*)(q0 + 2 * tig + 8);
            qa[ks][3] = *(const uint32_t*)(q1 + 2 * tig + 8);
        }

        // ldmatrix per-thread offsets (in halves)
        const int kq_off = (lane & 7) * HS + (lane >> 3) * 8;
        const int vv_off = lane * HS;

        // prologue: 2-deep prefetch
        issue_stage(kt0 * 64, kt0 & 1);
        if (kt0 + 1 < kt1) issue_stage((kt0 + 1) * 64, (kt0 + 1) & 1);
        else               cp_commit();

        for (int kt = kt0; kt < kt1; kt++) {
            cp_wait<1>();          // stage kt arrived
            __syncthreads();

            const uint32_t KsA = smaddr(Kb + (kt & 1) * 64 * HS);
            const uint32_t VsA = smaddr(Vb + (kt & 1) * 64 * HS);

            // -------- S = Q K^T  (16x64 per warp; log2-domain scores) --------
            float s[8][4];
#pragma unroll
            for (int ni = 0; ni < 8; ni++)
#pragma unroll
                for (int j = 0; j < 4; j++) s[ni][j] = 0.f;

#pragma unroll
            for (int ni = 0; ni < 8; ni++) {
                const uint32_t base = KsA + (uint32_t)(ni * 8 * HS + kq_off) * 2;
#pragma unroll
                for (int kc = 0; kc < 4; kc++) {
                    uint32_t r0, r1, r2, r3;
                    ldsm4(r0, r1, r2, r3, base + kc * 64);
                    uint32_t b01[2] = {r0, r1}, b23[2] = {r2, r3};
                    mma16(s[ni], qa[2 * kc],     b01);
                    mma16(s[ni], qa[2 * kc + 1], b23);
                }
            }

            // -------- causal mask (diagonal tile only) --------
            if (kt == qtile) {
                const int r0l = rb + g, r1l = rb + g + 8;
#pragma unroll
                for (int ni = 0; ni < 8; ni++) {
                    const int c = ni * 8 + 2 * tig;
                    s[ni][0] = (c     <= r0l) ? s[ni][0] : -INFINITY;
                    s[ni][1] = (c + 1 <= r0l) ? s[ni][1] : -INFINITY;
                    s[ni][2] = (c     <= r1l) ? s[ni][2] : -INFINITY;
                    s[ni][3] = (c + 1 <= r1l) ? s[ni][3] : -INFINITY;
                }
            }

            // -------- online softmax (log2 domain, single EX2 per element) ----
#pragma unroll
            for (int h = 0; h < 2; h++) {
                float tm = -INFINITY;
#pragma unroll
                for (int ni = 0; ni < 8; ni++)
                    tm = fmaxf(tm, fmaxf(s[ni][2 * h], s[ni][2 * h + 1]));
                tm = fmaxf(tm, __shfl_xor_sync(0xffffffffu, tm, 1));
                tm = fmaxf(tm, __shfl_xor_sync(0xffffffffu, tm, 2));

                const float mn = fmaxf(mr[h], tm);
                const float alpha = ex2(mr[h] - mn);
                mr[h] = mn;

                float rs = 0.f;
#pragma unroll
                for (int ni = 0; ni < 8; ni++) {
                    float p0 = ex2(s[ni][2 * h]     - mn);
                    float p1 = ex2(s[ni][2 * h + 1] - mn);
                    s[ni][2 * h] = p0; s[ni][2 * h + 1] = p1;
                    rs += p0 + p1;
                }
                rs += __shfl_xor_sync(0xffffffffu, rs, 1);
                rs += __shfl_xor_sync(0xffffffffu, rs, 2);
                lr[h] = lr[h] * alpha + rs;

#pragma unroll
                for (int nt = 0; nt < 16; nt++) {
                    o[nt][2 * h]     *= alpha;
                    o[nt][2 * h + 1] *= alpha;
                }
            }

            // -------- P -> fp16 A-fragments --------
            uint32_t pa[4][4];
#pragma unroll
            for (int js = 0; js < 4; js++) {
                pa[js][0] = ph2(s[2 * js][0],     s[2 * js][1]);
                pa[js][1] = ph2(s[2 * js][2],     s[2 * js][3]);
                pa[js][2] = ph2(s[2 * js + 1][0], s[2 * js + 1][1]);
                pa[js][3] = ph2(s[2 * js + 1][2], s[2 * js + 1][3]);
            }

            // -------- O += P V  (16x128 per warp) --------
#pragma unroll
            for (int nt = 0; nt < 16; nt++) {
                const uint32_t base = VsA + (uint32_t)(vv_off + nt * 8) * 2;
#pragma unroll
                for (int kc = 0; kc < 2; kc++) {
                    uint32_t r0, r1, r2, r3;
                    ldsm4t(r0, r1, r2, r3, base + kc * (32 * HS * 2));
                    uint32_t b01[2] = {r0, r1}, b23[2] = {r2, r3};
                    mma16(o[nt], pa[2 * kc],     b01);
                    mma16(o[nt], pa[2 * kc + 1], b23);
                }
            }

            // -------- all warps done reading stage kt; refill its buffer ------
            __syncthreads();
            if (kt + 2 < kt1) issue_stage((kt + 2) * 64, kt & 1);
            else              cp_commit();    // keep wait<1> invariant exact
        }

        cp_wait<0>();
    }

    // -------- epilogue: write partial (o, m, l); m in log2 domain --------
    const size_t pidx = ((size_t)(b * NQT + qtile) * 2 + half);
    float* Po = g_Po + pidx * (64 * HDIM);
#pragma unroll
    for (int nt = 0; nt < 16; nt++) {
        const int c = nt * 8 + 2 * tig;
        *(float2*)(Po + (rb + g)     * HDIM + c) = make_float2(o[nt][0], o[nt][1]);
        *(float2*)(Po + (rb + g + 8) * HDIM + c) = make_float2(o[nt][2], o[nt][3]);
    }
    if (tig == 0) {
        g_Pm[pidx * 64 + rb + g]     = mr[0];
        g_Pm[pidx * 64 + rb + g + 8] = mr[1];
        g_Pl[pidx * 64 + rb + g]     = lr[0];
        g_Pl[pidx * 64 + rb + g + 8] = lr[1];
    }
}

// ======================= split-K merge =========================
// grid (NQT*4, NB), 256 threads; each block merges a 16-row slab of one qtile.
__global__ __launch_bounds__(256) void merge_kernel(float* __restrict__ Out)
{
    const int q = blockIdx.x >> 2, quarter = blockIdx.x & 3, b = blockIdx.y;
    const size_t base = (size_t)(b * NQT + q) * 2;
    const float* o0 = g_Po + base * (64 * HDIM);
    const float* o1 = o0 + 64 * HDIM;

    const int t = threadIdx.x;
    const int r  = quarter * 16 + (t >> 4);   // 16 rows per block, 16 thr/row
    const int c0 = (t & 15) * 8;              // 8 cols per thread

    const float m0 = g_Pm[base * 64 + r], m1 = g_Pm[(base + 1) * 64 + r];
    const float l0 = g_Pl[base * 64 + r], l1 = g_Pl[(base + 1) * 64 + r];
    const float M  = fmaxf(m0, m1);
    const float w0 = ex2(m0 - M), w1 = ex2(m1 - M);   // log2-domain maxima
    const float invL = 1.0f / (l0 * w0 + l1 * w1);
    const float W0 = w0 * invL, W1 = w1 * invL;

    float* O = Out + (size_t)b * SEQ * HDIM + (size_t)(q * 64 + r) * HDIM;
#pragma unroll
    for (int i = 0; i < 8; i += 4) {
        float4 a  = *(const float4*)(o0 + r * HDIM + c0 + i);
        float4 bb = *(const float4*)(o1 + r * HDIM + c0 + i);
        float4 res;
        res.x = a.x * W0 + bb.x * W1;
        res.y = a.y * W0 + bb.y * W1;
        res.z = a.z * W0 + bb.z * W1;
        res.w = a.w * W0 + bb.w * W1;
        *(float4*)(O + c0 + i) = res;
    }
}

// =========================== launch =============================
extern "C" void kernel_launch(void* const* d_in, const int* in_sizes, int n_in,
                              void* d_out, int out_size)
{
    (void)in_sizes; (void)n_in; (void)out_size;
    const float* X  = (const float*)d_in[0];
    const float* Wq = (const float*)d_in[1];
    const float* Wk = (const float*)d_in[2];
    const float* Wv = (const float*)d_in[3];
    float* Out = (float*)d_out;

    static int attr_set = 0;
    if (!attr_set) {
        cudaFuncSetAttribute(fused_proj_kernel,
                             cudaFuncAttributeMaxDynamicSharedMemorySize,
                             FUSED_SMEM);
        cudaFuncSetAttribute(attn_kernel,
                             cudaFuncAttributeMaxDynamicSharedMemorySize,
                             ATT_SMEM);
        attr_set = 1;
    }

    // W fp32 -> fp16 (concat layout)
    dim3 wgrid(DDIM * HDIM / (256 * 8), 3);
    convert_W_kernel<<<wgrid, 256>>>(Wq, Wk, Wv);

    // Fused QKV projection (reads fp32 X once)
    fused_proj_kernel<<<BSTOT / 64, 512, FUSED_SMEM>>>(X);

    // Flash attention, split-K halves
    dim3 agrid(128, NB);
    attn_kernel<<<agrid, 128, ATT_SMEM>>>();

    // Merge halves (4 blocks per qtile)
    dim3 mgrid(NQT * 4, NB);
    merge_kernel<<<mgrid, 256>>>(Out);
}

// round 14
// speedup vs baseline: 1.0884x; 1.0286x over previous
#include <cuda_runtime.h>
#include <cuda_fp16.h>
#include <math.h>
#include <stdint.h>

// Problem shape (fixed by the dataset)
#define NB      4
#define SEQ     4096
#define DDIM    1024
#define HDIM    128
#define BSTOT   (NB * SEQ)          // 16384 rows
#define NQT     64                  // q-tiles per batch (SEQ/64)

// ---------------- scratch (no cudaMalloc allowed) ----------------
__device__ __half g_Wh[3 * DDIM * HDIM];    // fp16 Wq|Wk|Wv
__device__ __half g_Qh[BSTOT * HDIM];       // fp16 Q (pre-scaled by log2e/sqrt(128))
__device__ __half g_Kh[BSTOT * HDIM];
__device__ __half g_Vh[BSTOT * HDIM];
// split-K partials: [b][qtile][half]{ o:64x128, m:64, l:64 }  (m in log2 domain)
__device__ float g_Po[NB * NQT * 2 * 64 * HDIM];
__device__ float g_Pm[NB * NQT * 2 * 64];
__device__ float g_Pl[NB * NQT * 2 * 64];

// ------------------- helpers -------------------
// fp16: D += A(16x16, row) * B(16x8, col), fp32 accum
__device__ __forceinline__ void mma16(float* c, const uint32_t* a, const uint32_t* b) {
    asm volatile("mma.sync.aligned.m16n8k16.row.col.f32.f16.f16.f32 "
        "{%0,%1,%2,%3}, {%4,%5,%6,%7}, {%8,%9}, {%0,%1,%2,%3};"
        : "+f"(c[0]), "+f"(c[1]), "+f"(c[2]), "+f"(c[3])
        : "r"(a[0]), "r"(a[1]), "r"(a[2]), "r"(a[3]), "r"(b[0]), "r"(b[1]));
}
__device__ __forceinline__ void ldsm4(uint32_t& r0, uint32_t& r1, uint32_t& r2, uint32_t& r3,
                                      uint32_t addr) {
    asm volatile("ldmatrix.sync.aligned.m8n8.x4.shared.b16 {%0,%1,%2,%3}, [%4];"
        : "=r"(r0), "=r"(r1), "=r"(r2), "=r"(r3) : "r"(addr));
}
__device__ __forceinline__ void ldsm4t(uint32_t& r0, uint32_t& r1, uint32_t& r2, uint32_t& r3,
                                       uint32_t addr) {
    asm volatile("ldmatrix.sync.aligned.m8n8.x4.trans.shared.b16 {%0,%1,%2,%3}, [%4];"
        : "=r"(r0), "=r"(r1), "=r"(r2), "=r"(r3) : "r"(addr));
}
// pack two f32 -> f16x2 (lo = first element)
__device__ __forceinline__ uint32_t ph2(float lo, float hi) {
    uint32_t r; asm("cvt.rn.f16x2.f32 %0, %1, %2;" : "=r"(r) : "f"(hi), "f"(lo)); return r;
}
// 2^x, single MUFU op (exp done in log2 domain)
__device__ __forceinline__ float ex2(float x) {
    float r; asm("ex2.approx.ftz.f32 %0, %1;" : "=f"(r) : "f"(x)); return r;
}
__device__ __forceinline__ uint32_t smaddr(const void* p) {
    return (uint32_t)__cvta_generic_to_shared(p);
}
__device__ __forceinline__ void cp16(uint32_t s, const void* g) {
    asm volatile("cp.async.ca.shared.global [%0], [%1], 16;" :: "r"(s), "l"(g));
}
__device__ __forceinline__ void cp_commit() {
    asm volatile("cp.async.commit_group;");
}
template <int N>
__device__ __forceinline__ void cp_wait() {
    asm volatile("cp.async.wait_group %0;" :: "n"(N));
}

// ======================= W fp32 -> fp16 =========================
__global__ __launch_bounds__(256) void convert_W_kernel(
    const float* __restrict__ Wq, const float* __restrict__ Wk,
    const float* __restrict__ Wv)
{
    const float* W = (blockIdx.y == 0) ? Wq : ((blockIdx.y == 1) ? Wk : Wv);
    size_t i = ((size_t)blockIdx.x * 256 + threadIdx.x) * 8;
    float4 a = *(const float4*)(W + i);
    float4 b = *(const float4*)(W + i + 4);
    uint4 o;
    o.x = ph2(a.x, a.y); o.y = ph2(a.z, a.w);
    o.z = ph2(b.x, b.y); o.w = ph2(b.z, b.w);
    *(uint4*)(g_Wh + (size_t)blockIdx.y * DDIM * HDIM + i) = o;
}

// ======================= fused QKV projection =========================
// [Q|K|V][64 rows, 384 cols] = X[64,1024] (fp32, converted in-kernel) @ Wh[1024,384].
// 256 thr = 8 warps: wm=warp&3 (16 rows), wn=warp>>2 (192 cols = 24 n-tiles).
// launch_bounds(256,2): 2 CTAs/SM -> 256 CTAs fit in ONE wave (296 slots).
#define FXS 40    // X fp16 smem stride (halves)
#define FWS 392   // W fp16 smem stride (halves)
#define FUSED_SMEM ((2 * 64 * FXS + 2 * 32 * FWS) * 2)   // 60416 B

__global__ __launch_bounds__(256, 2) void fused_proj_kernel(const float* __restrict__ X)
{
    extern __shared__ __half fsm[];
    __half* Xb = fsm;                    // [2][64*FXS]
    __half* Wb = fsm + 2 * 64 * FXS;     // [2][32*FWS]

    const int tid  = threadIdx.x;
    const int warp = tid >> 5, lane = tid & 31;
    const int g = lane >> 2, tig = lane & 3;
    const int wm = warp & 3;      // 4 M-groups x 16 rows
    const int wn = warp >> 2;     // 2 N-groups x 192 cols
    const int row0 = blockIdx.x * 64;

    auto issue_W = [&](int k0, int s) {
        __half* Wd = Wb + s * 32 * FWS;
#pragma unroll
        for (int c = tid; c < 1536; c += 256) {     // 32 rows x 48 chunks of 8 halves
            int r = c / 48, cc = c % 48;
            int mat = cc >> 4, col = (cc & 15) * 8;
            cp16(smaddr(Wd + r * FWS + cc * 8),
                 g_Wh + (size_t)mat * DDIM * HDIM + (size_t)(k0 + r) * HDIM + col);
        }
        cp_commit();
    };

    // X staging: two float4 per thread per stage (64 rows x 32 cols)
    const int xr = tid >> 2;              // 64 rows, 4 threads per row
    const int xc0 = (tid & 3) * 4;        // cols xc0 and xc0+16

    float acc[24][4];
#pragma unroll
    for (int nt = 0; nt < 24; nt++)
#pragma unroll
        for (int j = 0; j < 4; j++) acc[nt][j] = 0.f;

    float4 xreg0 = *(const float4*)(X + (size_t)(row0 + xr) * DDIM + xc0);
    float4 xreg1 = *(const float4*)(X + (size_t)(row0 + xr) * DDIM + xc0 + 16);
    issue_W(0, 0);

    const int a_off = (lane & 15) * FXS + (lane >> 4) * 8;
    const int b_off = lane * FWS;

    for (int ki = 0; ki < 32; ki++) {
        {   // store prefetched X tile (cvt fp32->fp16) into buf ki&1
            __half* Xd = Xb + (ki & 1) * 64 * FXS + xr * FXS;
            uint2 p0; p0.x = ph2(xreg0.x, xreg0.y); p0.y = ph2(xreg0.z, xreg0.w);
            uint2 p1; p1.x = ph2(xreg1.x, xreg1.y); p1.y = ph2(xreg1.z, xreg1.w);
            *(uint2*)(Xd + xc0)      = p0;
            *(uint2*)(Xd + xc0 + 16) = p1;
        }
        if (ki < 31) {
            const float* Xr = X + (size_t)(row0 + xr) * DDIM + (ki + 1) * 32;
            xreg0 = *(const float4*)(Xr + xc0);
            xreg1 = *(const float4*)(Xr + xc0 + 16);
            issue_W((ki + 1) * 32, (ki + 1) & 1);
            cp_wait<1>();
        } else {
            cp_wait<0>();
        }
        __syncthreads();

        const uint32_t XsA = smaddr(Xb + (ki & 1) * 64 * FXS);
        const uint32_t WsA = smaddr(Wb + (ki & 1) * 32 * FWS);

        uint32_t a0[4], a1[4];
        ldsm4(a0[0], a0[1], a0[2], a0[3], XsA + (uint32_t)(wm * 16 * FXS + a_off) * 2);
        ldsm4(a1[0], a1[1], a1[2], a1[3], XsA + (uint32_t)(wm * 16 * FXS + a_off + 16) * 2);
#pragma unroll
        for (int nt = 0; nt < 24; nt++) {
            uint32_t r0, r1, r2, r3;
            ldsm4t(r0, r1, r2, r3, WsA + (uint32_t)(b_off + wn * 192 + nt * 8) * 2);
            uint32_t b01[2] = {r0, r1}, b23[2] = {r2, r3};
            mma16(acc[nt], a0, b01);
            mma16(acc[nt], a1, b23);
        }
        __syncthreads();
    }

    // epilogue: route each n-tile to Q/K/V; Q pre-scaled into log2 domain
    const float qsc = 0.088388347648318447f * 1.4426950408889634f;
    const int r = row0 + wm * 16 + g;
#pragma unroll
    for (int nt = 0; nt < 24; nt++) {
        const int ncol = wn * 192 + nt * 8 + 2 * tig;
        const int mat = ncol >> 7, col = ncol & 127;
        __half* Outh = (mat == 0) ? g_Qh : ((mat == 1) ? g_Kh : g_Vh);
        const float sc = (mat == 0) ? qsc : 1.0f;
        *(uint32_t*)(Outh + (size_t)r       * HDIM + col) = ph2(acc[nt][0] * sc, acc[nt][1] * sc);
        *(uint32_t*)(Outh + (size_t)(r + 8) * HDIM + col) = ph2(acc[nt][2] * sc, acc[nt][3] * sc);
    }
}

// ======================= flash attention (split-K) ========================
// grid (128, NB): bx -> qtile = 63-(bx>>1), half = bx&1.
// Q in regs, K+V joint double-buffered stages, 2-deep prefetch;
// launch_bounds(128,3) for 3 CTAs/SM; softmax in log2 domain (single EX2).
#define HS 136                       // half-stride per smem row (272 B)
#define ATT_SMEM (4 * 64 * HS * 2)   // 2 K bufs + 2 V bufs = 69632 B

__global__ __launch_bounds__(128, 3) void attn_kernel()
{
    extern __shared__ __half hsm[];
    __half* Kb = hsm;                  // [2][64*HS]
    __half* Vb = hsm + 2 * 64 * HS;    // [2][64*HS]

    const int tid  = threadIdx.x;
    const int warp = tid >> 5, lane = tid & 31;
    const int g = lane >> 2, tig = lane & 3;
    const int rb = warp * 16;
    const int b  = blockIdx.y;

    const __half* Q = g_Qh + (size_t)b * SEQ * HDIM;
    const __half* K = g_Kh + (size_t)b * SEQ * HDIM;
    const __half* V = g_Vh + (size_t)b * SEQ * HDIM;

    const int qtile = 63 - ((int)blockIdx.x >> 1);   // longest first
    const int half  = (int)blockIdx.x & 1;
    const int qbase = qtile * 64;
    const int n  = qtile + 1;
    const int n0 = (n + 1) >> 1;
    const int kt0 = half ? n0 : 0;
    const int kt1 = half ? n  : n0;

    auto issue_stage = [&](int kbase, int s) {
        __half* Kd = Kb + s * 64 * HS;
        __half* Vd = Vb + s * 64 * HS;
#pragma unroll
        for (int c = tid; c < 1024; c += 128) {
            int r = c >> 4, c8 = c & 15;
            cp16(smaddr(Kd + r * HS + c8 * 8),
                 K + (size_t)(kbase + r) * HDIM + c8 * 8);
            cp16(smaddr(Vd + r * HS + c8 * 8),
                 V + (size_t)(kbase + r) * HDIM + c8 * 8);
        }
        cp_commit();
    };

    float o[16][4];
#pragma unroll
    for (int nt = 0; nt < 16; nt++)
#pragma unroll
        for (int j = 0; j < 4; j++) o[nt][j] = 0.f;
    float mr[2] = {-INFINITY, -INFINITY};
    float lr[2] = {0.f, 0.f};

    if (kt0 < kt1) {
        // Q -> register A-fragments (fp16, log2-prescaled in gmem)
        uint32_t qa[8][4];
#pragma unroll
        for (int ks = 0; ks < 8; ks++) {
            const __half* q0 = Q + (size_t)(qbase + rb + g)     * HDIM + ks * 16;
            const __half* q1 = Q + (size_t)(qbase + rb + g + 8) * HDIM + ks * 16;
            qa[ks][0] = *(const uint32_t*)(q0 + 2 * tig);
            qa[ks][1] = *(const uint32_t*)(q1 + 2 * tig);
            qa[ks][2] = *(const uint32_t*)(q0 + 2 * tig + 8);
            qa[ks][3] = *(const uint32_t*)(q1 + 2 * tig + 8);
        }

        // ldmatrix per-thread offsets (in halves)
        const int kq_off = (lane & 7) * HS + (lane >> 3) * 8;
        const int vv_off = lane * HS;

        // prologue: 2-deep prefetch
        issue_stage(kt0 * 64, kt0 & 1);
        if (kt0 + 1 < kt1) issue_stage((kt0 + 1) * 64, (kt0 + 1) & 1);
        else               cp_commit();

        for (int kt = kt0; kt < kt1; kt++) {
            cp_wait<1>();          // stage kt arrived
            __syncthreads();

            const uint32_t KsA = smaddr(Kb + (kt & 1) * 64 * HS);
            const uint32_t VsA = smaddr(Vb + (kt & 1) * 64 * HS);

            // -------- S = Q K^T  (16x64 per warp; log2-domain scores) --------
            float s[8][4];
#pragma unroll
            for (int ni = 0; ni < 8; ni++)
#pragma unroll
                for (int j = 0; j < 4; j++) s[ni][j] = 0.f;

#pragma unroll
            for (int ni = 0; ni < 8; ni++) {
                const uint32_t base = KsA + (uint32_t)(ni * 8 * HS + kq_off) * 2;
#pragma unroll
                for (int kc = 0; kc < 4; kc++) {
                    uint32_t r0, r1, r2, r3;
                    ldsm4(r0, r1, r2, r3, base + kc * 64);
                    uint32_t b01[2] = {r0, r1}, b23[2] = {r2, r3};
                    mma16(s[ni], qa[2 * kc],     b01);
                    mma16(s[ni], qa[2 * kc + 1], b23);
                }
            }

            // -------- causal mask (diagonal tile only) --------
            if (kt == qtile) {
                const int r0l = rb + g, r1l = rb + g + 8;
#pragma unroll
                for (int ni = 0; ni < 8; ni++) {
                    const int c = ni * 8 + 2 * tig;
                    s[ni][0] = (c     <= r0l) ? s[ni][0] : -INFINITY;
                    s[ni][1] = (c + 1 <= r0l) ? s[ni][1] : -INFINITY;
                    s[ni][2] = (c     <= r1l) ? s[ni][2] : -INFINITY;
                    s[ni][3] = (c + 1 <= r1l) ? s[ni][3] : -INFINITY;
                }
            }

            // -------- online softmax (log2 domain, single EX2 per element) ----
#pragma unroll
            for (int h = 0; h < 2; h++) {
                float tm = -INFINITY;
#pragma unroll
                for (int ni = 0; ni < 8; ni++)
                    tm = fmaxf(tm, fmaxf(s[ni][2 * h], s[ni][2 * h + 1]));
                tm = fmaxf(tm, __shfl_xor_sync(0xffffffffu, tm, 1));
                tm = fmaxf(tm, __shfl_xor_sync(0xffffffffu, tm, 2));

                const float mn = fmaxf(mr[h], tm);
                const float alpha = ex2(mr[h] - mn);
                mr[h] = mn;

                float rs = 0.f;
#pragma unroll
                for (int ni = 0; ni < 8; ni++) {
                    float p0 = ex2(s[ni][2 * h]     - mn);
                    float p1 = ex2(s[ni][2 * h + 1] - mn);
                    s[ni][2 * h] = p0; s[ni][2 * h + 1] = p1;
                    rs += p0 + p1;
                }
                rs += __shfl_xor_sync(0xffffffffu, rs, 1);
                rs += __shfl_xor_sync(0xffffffffu, rs, 2);
                lr[h] = lr[h] * alpha + rs;

#pragma unroll
                for (int nt = 0; nt < 16; nt++) {
                    o[nt][2 * h]     *= alpha;
                    o[nt][2 * h + 1] *= alpha;
                }
            }

            // -------- P -> fp16 A-fragments --------
            uint32_t pa[4][4];
#pragma unroll
            for (int js = 0; js < 4; js++) {
                pa[js][0] = ph2(s[2 * js][0],     s[2 * js][1]);
                pa[js][1] = ph2(s[2 * js][2],     s[2 * js][3]);
                pa[js][2] = ph2(s[2 * js + 1][0], s[2 * js + 1][1]);
                pa[js][3] = ph2(s[2 * js + 1][2], s[2 * js + 1][3]);
            }

            // -------- O += P V  (16x128 per warp) --------
#pragma unroll
            for (int nt = 0; nt < 16; nt++) {
                const uint32_t base = VsA + (uint32_t)(vv_off + nt * 8) * 2;
#pragma unroll
                for (int kc = 0; kc < 2; kc++) {
                    uint32_t r0, r1, r2, r3;
                    ldsm4t(r0, r1, r2, r3, base + kc * (32 * HS * 2));
                    uint32_t b01[2] = {r0, r1}, b23[2] = {r2, r3};
                    mma16(o[nt], pa[2 * kc],     b01);
                    mma16(o[nt], pa[2 * kc + 1], b23);
                }
            }

            // -------- all warps done reading stage kt; refill its buffer ------
            __syncthreads();
            if (kt + 2 < kt1) issue_stage((kt + 2) * 64, kt & 1);
            else              cp_commit();    // keep wait<1> invariant exact
        }

        cp_wait<0>();
    }

    // -------- epilogue: write partial (o, m, l); m in log2 domain --------
    const size_t pidx = ((size_t)(b * NQT + qtile) * 2 + half);
    float* Po = g_Po + pidx * (64 * HDIM);
#pragma unroll
    for (int nt = 0; nt < 16; nt++) {
        const int c = nt * 8 + 2 * tig;
        *(float2*)(Po + (rb + g)     * HDIM + c) = make_float2(o[nt][0], o[nt][1]);
        *(float2*)(Po + (rb + g + 8) * HDIM + c) = make_float2(o[nt][2], o[nt][3]);
    }
    if (tig == 0) {
        g_Pm[pidx * 64 + rb + g]     = mr[0];
        g_Pm[pidx * 64 + rb + g + 8] = mr[1];
        g_Pl[pidx * 64 + rb + g]     = lr[0];
        g_Pl[pidx * 64 + rb + g + 8] = lr[1];
    }
}

// ======================= split-K merge =========================
// grid (NQT*8, NB), 256 threads; each block merges an 8-row slab of one qtile.
__global__ __launch_bounds__(256) void merge_kernel(float* __restrict__ Out)
{
    const int q = blockIdx.x >> 3, oct = blockIdx.x & 7, b = blockIdx.y;
    const size_t base = (size_t)(b * NQT + q) * 2;
    const float* o0 = g_Po + base * (64 * HDIM);
    const float* o1 = o0 + 64 * HDIM;

    const int t = threadIdx.x;
    const int r  = oct * 8 + (t >> 5);    // 8 rows per block, 32 thr/row
    const int c0 = (t & 31) * 4;          // one float4 per thread

    const float m0 = g_Pm[base * 64 + r], m1 = g_Pm[(base + 1) * 64 + r];
    const float l0 = g_Pl[base * 64 + r], l1 = g_Pl[(base + 1) * 64 + r];
    const float M  = fmaxf(m0, m1);
    const float w0 = ex2(m0 - M), w1 = ex2(m1 - M);   // log2-domain maxima
    const float invL = 1.0f / (l0 * w0 + l1 * w1);
    const float W0 = w0 * invL, W1 = w1 * invL;

    float* O = Out + (size_t)b * SEQ * HDIM + (size_t)(q * 64 + r) * HDIM;
    float4 a  = *(const float4*)(o0 + r * HDIM + c0);
    float4 bb = *(const float4*)(o1 + r * HDIM + c0);
    float4 res;
    res.x = a.x * W0 + bb.x * W1;
    res.y = a.y * W0 + bb.y * W1;
    res.z = a.z * W0 + bb.z * W1;
    res.w = a.w * W0 + bb.w * W1;
    *(float4*)(O + c0) = res;
}

// =========================== launch =============================
extern "C" void kernel_launch(void* const* d_in, const int* in_sizes, int n_in,
                              void* d_out, int out_size)
{
    (void)in_sizes; (void)n_in; (void)out_size;
    const float* X  = (const float*)d_in[0];
    const float* Wq = (const float*)d_in[1];
    const float* Wk = (const float*)d_in[2];
    const float* Wv = (const float*)d_in[3];
    float* Out = (float*)d_out;

    static int attr_set = 0;
    if (!attr_set) {
        cudaFuncSetAttribute(fused_proj_kernel,
                             cudaFuncAttributeMaxDynamicSharedMemorySize,
                             FUSED_SMEM);
        cudaFuncSetAttribute(attn_kernel,
                             cudaFuncAttributeMaxDynamicSharedMemorySize,
                             ATT_SMEM);
        attr_set = 1;
    }

    // W fp32 -> fp16 (concat layout)
    dim3 wgrid(DDIM * HDIM / (256 * 8), 3);
    convert_W_kernel<<<wgrid, 256>>>(Wq, Wk, Wv);

    // Fused QKV projection (reads fp32 X once; one wave at 2 CTAs/SM)
    fused_proj_kernel<<<BSTOT / 64, 256, FUSED_SMEM>>>(X);

    // Flash attention, split-K halves
    dim3 agrid(128, NB);
    attn_kernel<<<agrid, 128, ATT_SMEM>>>();

    // Merge halves (8 blocks per qtile)
    dim3 mgrid(NQT * 8, NB);
    merge_kernel<<<mgrid, 256>>>(Out);
}

// round 15
// speedup vs baseline: 1.0943x; 1.0054x over previous
#include <cuda_runtime.h>
#include <cuda_fp16.h>
#include <math.h>
#include <stdint.h>

// Problem shape (fixed by the dataset)
#define NB      4
#define SEQ     4096
#define DDIM    1024
#define HDIM    128
#define BSTOT   (NB * SEQ)          // 16384 rows
#define NQT     64                  // q-tiles per batch (SEQ/64)
#define NCH     4                   // max KV chunks per qtile
#define CHUNK   16                  // tile-steps per chunk

// ---------------- scratch (no cudaMalloc allowed) ----------------
__device__ __half g_Wh[3 * DDIM * HDIM];    // fp16 Wq|Wk|Wv
__device__ __half g_Qh[BSTOT * HDIM];       // fp16 Q (pre-scaled by log2e/sqrt(128))
__device__ __half g_Kh[BSTOT * HDIM];
__device__ __half g_Vh[BSTOT * HDIM];
// split-K partials: [b][qtile][chunk]{ o:64x128, m:64, l:64 }  (m in log2 domain)
__device__ float g_Po[NB * NQT * NCH * 64 * HDIM];
__device__ float g_Pm[NB * NQT * NCH * 64];
__device__ float g_Pl[NB * NQT * NCH * 64];

// ------------------- helpers -------------------
// fp16: D += A(16x16, row) * B(16x8, col), fp32 accum
__device__ __forceinline__ void mma16(float* c, const uint32_t* a, const uint32_t* b) {
    asm volatile("mma.sync.aligned.m16n8k16.row.col.f32.f16.f16.f32 "
        "{%0,%1,%2,%3}, {%4,%5,%6,%7}, {%8,%9}, {%0,%1,%2,%3};"
        : "+f"(c[0]), "+f"(c[1]), "+f"(c[2]), "+f"(c[3])
        : "r"(a[0]), "r"(a[1]), "r"(a[2]), "r"(a[3]), "r"(b[0]), "r"(b[1]));
}
__device__ __forceinline__ void ldsm4(uint32_t& r0, uint32_t& r1, uint32_t& r2, uint32_t& r3,
                                      uint32_t addr) {
    asm volatile("ldmatrix.sync.aligned.m8n8.x4.shared.b16 {%0,%1,%2,%3}, [%4];"
        : "=r"(r0), "=r"(r1), "=r"(r2), "=r"(r3) : "r"(addr));
}
__device__ __forceinline__ void ldsm4t(uint32_t& r0, uint32_t& r1, uint32_t& r2, uint32_t& r3,
                                       uint32_t addr) {
    asm volatile("ldmatrix.sync.aligned.m8n8.x4.trans.shared.b16 {%0,%1,%2,%3}, [%4];"
        : "=r"(r0), "=r"(r1), "=r"(r2), "=r"(r3) : "r"(addr));
}
// pack two f32 -> f16x2 (lo = first element)
__device__ __forceinline__ uint32_t ph2(float lo, float hi) {
    uint32_t r; asm("cvt.rn.f16x2.f32 %0, %1, %2;" : "=r"(r) : "f"(hi), "f"(lo)); return r;
}
// 2^x, single MUFU op (exp done in log2 domain)
__device__ __forceinline__ float ex2(float x) {
    float r; asm("ex2.approx.ftz.f32 %0, %1;" : "=f"(r) : "f"(x)); return r;
}
__device__ __forceinline__ uint32_t smaddr(const void* p) {
    return (uint32_t)__cvta_generic_to_shared(p);
}
__device__ __forceinline__ void cp16(uint32_t s, const void* g) {
    asm volatile("cp.async.ca.shared.global [%0], [%1], 16;" :: "r"(s), "l"(g));
}
__device__ __forceinline__ void cp_commit() {
    asm volatile("cp.async.commit_group;");
}
template <int N>
__device__ __forceinline__ void cp_wait() {
    asm volatile("cp.async.wait_group %0;" :: "n"(N));
}

// ======================= W fp32 -> fp16 =========================
__global__ __launch_bounds__(256) void convert_W_kernel(
    const float* __restrict__ Wq, const float* __restrict__ Wk,
    const float* __restrict__ Wv)
{
    const float* W = (blockIdx.y == 0) ? Wq : ((blockIdx.y == 1) ? Wk : Wv);
    size_t i = ((size_t)blockIdx.x * 256 + threadIdx.x) * 8;
    float4 a = *(const float4*)(W + i);
    float4 b = *(const float4*)(W + i + 4);
    uint4 o;
    o.x = ph2(a.x, a.y); o.y = ph2(a.z, a.w);
    o.z = ph2(b.x, b.y); o.w = ph2(b.z, b.w);
    *(uint4*)(g_Wh + (size_t)blockIdx.y * DDIM * HDIM + i) = o;
}

// ======================= fused QKV projection =========================
// [Q|K|V][64 rows, 384 cols] = X[64,1024] (fp32, converted in-kernel) @ Wh[1024,384].
// 256 thr = 8 warps: wm=warp&3 (16 rows), wn=warp>>2 (192 cols = 24 n-tiles).
#define FXS 40    // X fp16 smem stride (halves)
#define FWS 392   // W fp16 smem stride (halves)
#define FUSED_SMEM ((2 * 64 * FXS + 2 * 32 * FWS) * 2)   // 60416 B

__global__ __launch_bounds__(256, 2) void fused_proj_kernel(const float* __restrict__ X)
{
    extern __shared__ __half fsm[];
    __half* Xb = fsm;                    // [2][64*FXS]
    __half* Wb = fsm + 2 * 64 * FXS;     // [2][32*FWS]

    const int tid  = threadIdx.x;
    const int warp = tid >> 5, lane = tid & 31;
    const int g = lane >> 2, tig = lane & 3;
    const int wm = warp & 3;      // 4 M-groups x 16 rows
    const int wn = warp >> 2;     // 2 N-groups x 192 cols
    const int row0 = blockIdx.x * 64;

    auto issue_W = [&](int k0, int s) {
        __half* Wd = Wb + s * 32 * FWS;
#pragma unroll
        for (int c = tid; c < 1536; c += 256) {     // 32 rows x 48 chunks of 8 halves
            int r = c / 48, cc = c % 48;
            int mat = cc >> 4, col = (cc & 15) * 8;
            cp16(smaddr(Wd + r * FWS + cc * 8),
                 g_Wh + (size_t)mat * DDIM * HDIM + (size_t)(k0 + r) * HDIM + col);
        }
        cp_commit();
    };

    // X staging: two float4 per thread per stage (64 rows x 32 cols)
    const int xr = tid >> 2;              // 64 rows, 4 threads per row
    const int xc0 = (tid & 3) * 4;        // cols xc0 and xc0+16

    float acc[24][4];
#pragma unroll
    for (int nt = 0; nt < 24; nt++)
#pragma unroll
        for (int j = 0; j < 4; j++) acc[nt][j] = 0.f;

    float4 xreg0 = *(const float4*)(X + (size_t)(row0 + xr) * DDIM + xc0);
    float4 xreg1 = *(const float4*)(X + (size_t)(row0 + xr) * DDIM + xc0 + 16);
    issue_W(0, 0);

    const int a_off = (lane & 15) * FXS + (lane >> 4) * 8;
    const int b_off = lane * FWS;

    for (int ki = 0; ki < 32; ki++) {
        {   // store prefetched X tile (cvt fp32->fp16) into buf ki&1
            __half* Xd = Xb + (ki & 1) * 64 * FXS + xr * FXS;
            uint2 p0; p0.x = ph2(xreg0.x, xreg0.y); p0.y = ph2(xreg0.z, xreg0.w);
            uint2 p1; p1.x = ph2(xreg1.x, xreg1.y); p1.y = ph2(xreg1.z, xreg1.w);
            *(uint2*)(Xd + xc0)      = p0;
            *(uint2*)(Xd + xc0 + 16) = p1;
        }
        if (ki < 31) {
            const float* Xr = X + (size_t)(row0 + xr) * DDIM + (ki + 1) * 32;
            xreg0 = *(const float4*)(Xr + xc0);
            xreg1 = *(const float4*)(Xr + xc0 + 16);
            issue_W((ki + 1) * 32, (ki + 1) & 1);
            cp_wait<1>();
        } else {
            cp_wait<0>();
        }
        __syncthreads();

        const uint32_t XsA = smaddr(Xb + (ki & 1) * 64 * FXS);
        const uint32_t WsA = smaddr(Wb + (ki & 1) * 32 * FWS);

        uint32_t a0[4], a1[4];
        ldsm4(a0[0], a0[1], a0[2], a0[3], XsA + (uint32_t)(wm * 16 * FXS + a_off) * 2);
        ldsm4(a1[0], a1[1], a1[2], a1[3], XsA + (uint32_t)(wm * 16 * FXS + a_off + 16) * 2);
#pragma unroll
        for (int nt = 0; nt < 24; nt++) {
            uint32_t r0, r1, r2, r3;
            ldsm4t(r0, r1, r2, r3, WsA + (uint32_t)(b_off + wn * 192 + nt * 8) * 2);
            uint32_t b01[2] = {r0, r1}, b23[2] = {r2, r3};
            mma16(acc[nt], a0, b01);
            mma16(acc[nt], a1, b23);
        }
        __syncthreads();
    }

    // epilogue: route each n-tile to Q/K/V; Q pre-scaled into log2 domain
    const float qsc = 0.088388347648318447f * 1.4426950408889634f;
    const int r = row0 + wm * 16 + g;
#pragma unroll
    for (int nt = 0; nt < 24; nt++) {
        const int ncol = wn * 192 + nt * 8 + 2 * tig;
        const int mat = ncol >> 7, col = ncol & 127;
        __half* Outh = (mat == 0) ? g_Qh : ((mat == 1) ? g_Kh : g_Vh);
        const float sc = (mat == 0) ? qsc : 1.0f;
        *(uint32_t*)(Outh + (size_t)r       * HDIM + col) = ph2(acc[nt][0] * sc, acc[nt][1] * sc);
        *(uint32_t*)(Outh + (size_t)(r + 8) * HDIM + col) = ph2(acc[nt][2] * sc, acc[nt][3] * sc);
    }
}

// ======================= flash attention (chunked split-K) =================
// grid (256, NB): bx -> qtile = 63-(bx>>2), chunk = bx&3.
// Each CTA handles kt in [chunk*16, min(chunk*16+16, qtile+1)) -- <=16 steps,
// bounding the makespan near the 18.7-steps/slot average. Empty chunks exit.
#define HS 136                       // half-stride per smem row (272 B)
#define ATT_SMEM (4 * 64 * HS * 2)   // 2 K bufs + 2 V bufs = 69632 B

__global__ __launch_bounds__(128, 3) void attn_kernel()
{
    extern __shared__ __half hsm[];
    __half* Kb = hsm;                  // [2][64*HS]
    __half* Vb = hsm + 2 * 64 * HS;    // [2][64*HS]

    const int tid  = threadIdx.x;
    const int warp = tid >> 5, lane = tid & 31;
    const int g = lane >> 2, tig = lane & 3;
    const int rb = warp * 16;
    const int b  = blockIdx.y;

    const int qtile = 63 - ((int)blockIdx.x >> 2);   // longest first
    const int chunk = (int)blockIdx.x & 3;
    const int n  = qtile + 1;
    const int kt0 = chunk * CHUNK;
    if (kt0 >= n) return;                            // empty chunk
    const int kt1 = (kt0 + CHUNK < n) ? kt0 + CHUNK : n;
    const int qbase = qtile * 64;

    const __half* Q = g_Qh + (size_t)b * SEQ * HDIM;
    const __half* K = g_Kh + (size_t)b * SEQ * HDIM;
    const __half* V = g_Vh + (size_t)b * SEQ * HDIM;

    auto issue_stage = [&](int kbase, int s) {
        __half* Kd = Kb + s * 64 * HS;
        __half* Vd = Vb + s * 64 * HS;
#pragma unroll
        for (int c = tid; c < 1024; c += 128) {
            int r = c >> 4, c8 = c & 15;
            cp16(smaddr(Kd + r * HS + c8 * 8),
                 K + (size_t)(kbase + r) * HDIM + c8 * 8);
            cp16(smaddr(Vd + r * HS + c8 * 8),
                 V + (size_t)(kbase + r) * HDIM + c8 * 8);
        }
        cp_commit();
    };

    float o[16][4];
#pragma unroll
    for (int nt = 0; nt < 16; nt++)
#pragma unroll
        for (int j = 0; j < 4; j++) o[nt][j] = 0.f;
    float mr[2] = {-INFINITY, -INFINITY};
    float lr[2] = {0.f, 0.f};

    {
        // Q -> register A-fragments (fp16, log2-prescaled in gmem)
        uint32_t qa[8][4];
#pragma unroll
        for (int ks = 0; ks < 8; ks++) {
            const __half* q0 = Q + (size_t)(qbase + rb + g)     * HDIM + ks * 16;
            const __half* q1 = Q + (size_t)(qbase + rb + g + 8) * HDIM + ks * 16;
            qa[ks][0] = *(const uint32_t*)(q0 + 2 * tig);
            qa[ks][1] = *(const uint32_t*)(q1 + 2 * tig);
            qa[ks][2] = *(const uint32_t*)(q0 + 2 * tig + 8);
            qa[ks][3] = *(const uint32_t*)(q1 + 2 * tig + 8);
        }

        // ldmatrix per-thread offsets (in halves)
        const int kq_off = (lane & 7) * HS + (lane >> 3) * 8;
        const int vv_off = lane * HS;

        // prologue: 2-deep prefetch
        issue_stage(kt0 * 64, kt0 & 1);
        if (kt0 + 1 < kt1) issue_stage((kt0 + 1) * 64, (kt0 + 1) & 1);
        else               cp_commit();

        for (int kt = kt0; kt < kt1; kt++) {
            cp_wait<1>();          // stage kt arrived
            __syncthreads();

            const uint32_t KsA = smaddr(Kb + (kt & 1) * 64 * HS);
            const uint32_t VsA = smaddr(Vb + (kt & 1) * 64 * HS);

            // -------- S = Q K^T  (16x64 per warp; log2-domain scores) --------
            float s[8][4];
#pragma unroll
            for (int ni = 0; ni < 8; ni++)
#pragma unroll
                for (int j = 0; j < 4; j++) s[ni][j] = 0.f;

#pragma unroll
            for (int ni = 0; ni < 8; ni++) {
                const uint32_t base = KsA + (uint32_t)(ni * 8 * HS + kq_off) * 2;
#pragma unroll
                for (int kc = 0; kc < 4; kc++) {
                    uint32_t r0, r1, r2, r3;
                    ldsm4(r0, r1, r2, r3, base + kc * 64);
                    uint32_t b01[2] = {r0, r1}, b23[2] = {r2, r3};
                    mma16(s[ni], qa[2 * kc],     b01);
                    mma16(s[ni], qa[2 * kc + 1], b23);
                }
            }

            // -------- causal mask (diagonal tile only) --------
            if (kt == qtile) {
                const int r0l = rb + g, r1l = rb + g + 8;
#pragma unroll
                for (int ni = 0; ni < 8; ni++) {
                    const int c = ni * 8 + 2 * tig;
                    s[ni][0] = (c     <= r0l) ? s[ni][0] : -INFINITY;
                    s[ni][1] = (c + 1 <= r0l) ? s[ni][1] : -INFINITY;
                    s[ni][2] = (c     <= r1l) ? s[ni][2] : -INFINITY;
                    s[ni][3] = (c + 1 <= r1l) ? s[ni][3] : -INFINITY;
                }
            }

            // -------- online softmax (log2 domain, single EX2 per element) ----
#pragma unroll
            for (int h = 0; h < 2; h++) {
                float tm = -INFINITY;
#pragma unroll
                for (int ni = 0; ni < 8; ni++)
                    tm = fmaxf(tm, fmaxf(s[ni][2 * h], s[ni][2 * h + 1]));
                tm = fmaxf(tm, __shfl_xor_sync(0xffffffffu, tm, 1));
                tm = fmaxf(tm, __shfl_xor_sync(0xffffffffu, tm, 2));

                const float mn = fmaxf(mr[h], tm);
                const float alpha = ex2(mr[h] - mn);
                mr[h] = mn;

                float rs = 0.f;
#pragma unroll
                for (int ni = 0; ni < 8; ni++) {
                    float p0 = ex2(s[ni][2 * h]     - mn);
                    float p1 = ex2(s[ni][2 * h + 1] - mn);
                    s[ni][2 * h] = p0; s[ni][2 * h + 1] = p1;
                    rs += p0 + p1;
                }
                rs += __shfl_xor_sync(0xffffffffu, rs, 1);
                rs += __shfl_xor_sync(0xffffffffu, rs, 2);
                lr[h] = lr[h] * alpha + rs;

#pragma unroll
                for (int nt = 0; nt < 16; nt++) {
                    o[nt][2 * h]     *= alpha;
                    o[nt][2 * h + 1] *= alpha;
                }
            }

            // -------- P -> fp16 A-fragments --------
            uint32_t pa[4][4];
#pragma unroll
            for (int js = 0; js < 4; js++) {
                pa[js][0] = ph2(s[2 * js][0],     s[2 * js][1]);
                pa[js][1] = ph2(s[2 * js][2],     s[2 * js][3]);
                pa[js][2] = ph2(s[2 * js + 1][0], s[2 * js + 1][1]);
                pa[js][3] = ph2(s[2 * js + 1][2], s[2 * js + 1][3]);
            }

            // -------- O += P V  (16x128 per warp) --------
#pragma unroll
            for (int nt = 0; nt < 16; nt++) {
                const uint32_t base = VsA + (uint32_t)(vv_off + nt * 8) * 2;
#pragma unroll
                for (int kc = 0; kc < 2; kc++) {
                    uint32_t r0, r1, r2, r3;
                    ldsm4t(r0, r1, r2, r3, base + kc * (32 * HS * 2));
                    uint32_t b01[2] = {r0, r1}, b23[2] = {r2, r3};
                    mma16(o[nt], pa[2 * kc],     b01);
                    mma16(o[nt], pa[2 * kc + 1], b23);
                }
            }

            // -------- all warps done reading stage kt; refill its buffer ------
            __syncthreads();
            if (kt + 2 < kt1) issue_stage((kt + 2) * 64, kt & 1);
            else              cp_commit();    // keep wait<1> invariant exact
        }

        cp_wait<0>();
    }

    // -------- epilogue: write partial (o, m, l); m in log2 domain --------
    const size_t pidx = ((size_t)(b * NQT + qtile) * NCH + chunk);
    float* Po = g_Po + pidx * (64 * HDIM);
#pragma unroll
    for (int nt = 0; nt < 16; nt++) {
        const int c = nt * 8 + 2 * tig;
        *(float2*)(Po + (rb + g)     * HDIM + c) = make_float2(o[nt][0], o[nt][1]);
        *(float2*)(Po + (rb + g + 8) * HDIM + c) = make_float2(o[nt][2], o[nt][3]);
    }
    if (tig == 0) {
        g_Pm[pidx * 64 + rb + g]     = mr[0];
        g_Pm[pidx * 64 + rb + g + 8] = mr[1];
        g_Pl[pidx * 64 + rb + g]     = lr[0];
        g_Pl[pidx * 64 + rb + g + 8] = lr[1];
    }
}

// ======================= split-K merge =========================
// grid (NQT*8, NB), 256 threads; each block merges an 8-row slab of one qtile,
// combining its nch = ceil((q+1)/CHUNK) chunk partials.
__global__ __launch_bounds__(256) void merge_kernel(float* __restrict__ Out)
{
    const int q = blockIdx.x >> 3, oct = blockIdx.x & 7, b = blockIdx.y;
    const int nch = (q + CHUNK) / CHUNK;      // ceil((q+1)/CHUNK)
    const size_t base = (size_t)(b * NQT + q) * NCH;

    const int t = threadIdx.x;
    const int r  = oct * 8 + (t >> 5);    // 8 rows per block, 32 thr/row
    const int c0 = (t & 31) * 4;          // one float4 per thread

    float m[NCH], l[NCH];
    float M = -INFINITY;
#pragma unroll
    for (int ch = 0; ch < NCH; ch++) {
        if (ch < nch) {
            m[ch] = g_Pm[(base + ch) * 64 + r];
            l[ch] = g_Pl[(base + ch) * 64 + r];
            M = fmaxf(M, m[ch]);
        }
    }
    float L = 0.f, w[NCH];
#pragma unroll
    for (int ch = 0; ch < NCH; ch++) {
        if (ch < nch) {
            w[ch] = ex2(m[ch] - M);
            L += l[ch] * w[ch];
        }
    }
    const float invL = 1.0f / L;

    float4 res = make_float4(0.f, 0.f, 0.f, 0.f);
#pragma unroll
    for (int ch = 0; ch < NCH; ch++) {
        if (ch < nch) {
            const float* Po = g_Po + (base + ch) * (64 * HDIM);
            float4 a = *(const float4*)(Po + r * HDIM + c0);
            const float W = w[ch];
            res.x += a.x * W; res.y += a.y * W;
            res.z += a.z * W; res.w += a.w * W;
        }
    }
    res.x *= invL; res.y *= invL; res.z *= invL; res.w *= invL;

    float* O = Out + (size_t)b * SEQ * HDIM + (size_t)(q * 64 + r) * HDIM;
    *(float4*)(O + c0) = res;
}

// =========================== launch =============================
extern "C" void kernel_launch(void* const* d_in, const int* in_sizes, int n_in,
                              void* d_out, int out_size)
{
    (void)in_sizes; (void)n_in; (void)out_size;
    const float* X  = (const float*)d_in[0];
    const float* Wq = (const float*)d_in[1];
    const float* Wk = (const float*)d_in[2];
    const float* Wv = (const float*)d_in[3];
    float* Out = (float*)d_out;

    static int attr_set = 0;
    if (!attr_set) {
        cudaFuncSetAttribute(fused_proj_kernel,
                             cudaFuncAttributeMaxDynamicSharedMemorySize,
                             FUSED_SMEM);
        cudaFuncSetAttribute(attn_kernel,
                             cudaFuncAttributeMaxDynamicSharedMemorySize,
                             ATT_SMEM);
        attr_set = 1;
    }

    // W fp32 -> fp16 (concat layout)
    dim3 wgrid(DDIM * HDIM / (256 * 8), 3);
    convert_W_kernel<<<wgrid, 256>>>(Wq, Wk, Wv);

    // Fused QKV projection (reads fp32 X once; one wave at 2 CTAs/SM)
    fused_proj_kernel<<<BSTOT / 64, 256, FUSED_SMEM>>>(X);

    // Flash attention, chunked split-K (<=16 steps per CTA)
    dim3 agrid(NQT * NCH, NB);
    attn_kernel<<<agrid, 128, ATT_SMEM>>>();

    // Merge chunk partials (8 blocks per qtile)
    dim3 mgrid(NQT * 8, NB);
    merge_kernel<<<mgrid, 256>>>(Out);
}

// round 16
// speedup vs baseline: 1.0990x; 1.0042x over previous
#include <cuda_runtime.h>
#include <cuda_fp16.h>
#include <math.h>
#include <stdint.h>

// Problem shape (fixed by the dataset)
#define NB      4
#define SEQ     4096
#define DDIM    1024
#define HDIM    128
#define BSTOT   (NB * SEQ)          // 16384 rows
#define NQT     64                  // q-tiles per batch (SEQ/64)
#define NCH     4                   // max KV chunks per qtile
#define CHUNK   16                  // tile-steps per chunk

// ---------------- scratch (no cudaMalloc allowed) ----------------
__device__ __half g_Wh[3 * DDIM * HDIM];    // fp16 Wq|Wk|Wv
__device__ __half g_Qh[BSTOT * HDIM];       // fp16 Q (pre-scaled by log2e/sqrt(128))
__device__ __half g_Kh[BSTOT * HDIM];
__device__ __half g_Vh[BSTOT * HDIM];
// split-K partials: [b][qtile][chunk]{ o:64x128, m:64, l:64 }  (m in log2 domain)
__device__ float g_Po[NB * NQT * NCH * 64 * HDIM];
__device__ float g_Pm[NB * NQT * NCH * 64];
__device__ float g_Pl[NB * NQT * NCH * 64];

// ------------------- helpers -------------------
// fp16: D += A(16x16, row) * B(16x8, col), fp32 accum
__device__ __forceinline__ void mma16(float* c, const uint32_t* a, const uint32_t* b) {
    asm volatile("mma.sync.aligned.m16n8k16.row.col.f32.f16.f16.f32 "
        "{%0,%1,%2,%3}, {%4,%5,%6,%7}, {%8,%9}, {%0,%1,%2,%3};"
        : "+f"(c[0]), "+f"(c[1]), "+f"(c[2]), "+f"(c[3])
        : "r"(a[0]), "r"(a[1]), "r"(a[2]), "r"(a[3]), "r"(b[0]), "r"(b[1]));
}
__device__ __forceinline__ void ldsm4(uint32_t& r0, uint32_t& r1, uint32_t& r2, uint32_t& r3,
                                      uint32_t addr) {
    asm volatile("ldmatrix.sync.aligned.m8n8.x4.shared.b16 {%0,%1,%2,%3}, [%4];"
        : "=r"(r0), "=r"(r1), "=r"(r2), "=r"(r3) : "r"(addr));
}
__device__ __forceinline__ void ldsm4t(uint32_t& r0, uint32_t& r1, uint32_t& r2, uint32_t& r3,
                                       uint32_t addr) {
    asm volatile("ldmatrix.sync.aligned.m8n8.x4.trans.shared.b16 {%0,%1,%2,%3}, [%4];"
        : "=r"(r0), "=r"(r1), "=r"(r2), "=r"(r3) : "r"(addr));
}
// pack two f32 -> f16x2 (lo = first element)
__device__ __forceinline__ uint32_t ph2(float lo, float hi) {
    uint32_t r; asm("cvt.rn.f16x2.f32 %0, %1, %2;" : "=r"(r) : "f"(hi), "f"(lo)); return r;
}
// 2^x, single MUFU op (exp done in log2 domain)
__device__ __forceinline__ float ex2(float x) {
    float r; asm("ex2.approx.ftz.f32 %0, %1;" : "=f"(r) : "f"(x)); return r;
}
__device__ __forceinline__ uint32_t smaddr(const void* p) {
    return (uint32_t)__cvta_generic_to_shared(p);
}
__device__ __forceinline__ void cp16(uint32_t s, const void* g) {
    asm volatile("cp.async.ca.shared.global [%0], [%1], 16;" :: "r"(s), "l"(g));
}
__device__ __forceinline__ void cp_commit() {
    asm volatile("cp.async.commit_group;");
}
template <int N>
__device__ __forceinline__ void cp_wait() {
    asm volatile("cp.async.wait_group %0;" :: "n"(N));
}

// ======================= W fp32 -> fp16 =========================
__global__ __launch_bounds__(256) void convert_W_kernel(
    const float* __restrict__ Wq, const float* __restrict__ Wk,
    const float* __restrict__ Wv)
{
    const float* W = (blockIdx.y == 0) ? Wq : ((blockIdx.y == 1) ? Wk : Wv);
    size_t i = ((size_t)blockIdx.x * 256 + threadIdx.x) * 8;
    float4 a = *(const float4*)(W + i);
    float4 b = *(const float4*)(W + i + 4);
    uint4 o;
    o.x = ph2(a.x, a.y); o.y = ph2(a.z, a.w);
    o.z = ph2(b.x, b.y); o.w = ph2(b.z, b.w);
    *(uint4*)(g_Wh + (size_t)blockIdx.y * DDIM * HDIM + i) = o;
}

// ======================= fused QKV projection =========================
// [Q|K|V][64 rows, 384 cols] = X[64,1024] (fp32, converted in-kernel) @ Wh[1024,384].
// 256 thr = 8 warps: wm=warp&3 (16 rows), wn=warp>>2 (192 cols = 24 n-tiles).
#define FXS 40    // X fp16 smem stride (halves)
#define FWS 392   // W fp16 smem stride (halves)
#define FUSED_SMEM ((2 * 64 * FXS + 2 * 32 * FWS) * 2)   // 60416 B

__global__ __launch_bounds__(256, 2) void fused_proj_kernel(const float* __restrict__ X)
{
    extern __shared__ __half fsm[];
    __half* Xb = fsm;                    // [2][64*FXS]
    __half* Wb = fsm + 2 * 64 * FXS;     // [2][32*FWS]

    const int tid  = threadIdx.x;
    const int warp = tid >> 5, lane = tid & 31;
    const int g = lane >> 2, tig = lane & 3;
    const int wm = warp & 3;      // 4 M-groups x 16 rows
    const int wn = warp >> 2;     // 2 N-groups x 192 cols
    const int row0 = blockIdx.x * 64;

    auto issue_W = [&](int k0, int s) {
        __half* Wd = Wb + s * 32 * FWS;
#pragma unroll
        for (int c = tid; c < 1536; c += 256) {     // 32 rows x 48 chunks of 8 halves
            int r = c / 48, cc = c % 48;
            int mat = cc >> 4, col = (cc & 15) * 8;
            cp16(smaddr(Wd + r * FWS + cc * 8),
                 g_Wh + (size_t)mat * DDIM * HDIM + (size_t)(k0 + r) * HDIM + col);
        }
        cp_commit();
    };

    // X staging: two float4 per thread per stage (64 rows x 32 cols)
    const int xr = tid >> 2;              // 64 rows, 4 threads per row
    const int xc0 = (tid & 3) * 4;        // cols xc0 and xc0+16

    float acc[24][4];
#pragma unroll
    for (int nt = 0; nt < 24; nt++)
#pragma unroll
        for (int j = 0; j < 4; j++) acc[nt][j] = 0.f;

    float4 xreg0 = *(const float4*)(X + (size_t)(row0 + xr) * DDIM + xc0);
    float4 xreg1 = *(const float4*)(X + (size_t)(row0 + xr) * DDIM + xc0 + 16);
    issue_W(0, 0);

    const int a_off = (lane & 15) * FXS + (lane >> 4) * 8;
    const int b_off = lane * FWS;

    for (int ki = 0; ki < 32; ki++) {
        {   // store prefetched X tile (cvt fp32->fp16) into buf ki&1
            __half* Xd = Xb + (ki & 1) * 64 * FXS + xr * FXS;
            uint2 p0; p0.x = ph2(xreg0.x, xreg0.y); p0.y = ph2(xreg0.z, xreg0.w);
            uint2 p1; p1.x = ph2(xreg1.x, xreg1.y); p1.y = ph2(xreg1.z, xreg1.w);
            *(uint2*)(Xd + xc0)      = p0;
            *(uint2*)(Xd + xc0 + 16) = p1;
        }
        if (ki < 31) {
            const float* Xr = X + (size_t)(row0 + xr) * DDIM + (ki + 1) * 32;
            xreg0 = *(const float4*)(Xr + xc0);
            xreg1 = *(const float4*)(Xr + xc0 + 16);
            issue_W((ki + 1) * 32, (ki + 1) & 1);
            cp_wait<1>();
        } else {
            cp_wait<0>();
        }
        __syncthreads();

        const uint32_t XsA = smaddr(Xb + (ki & 1) * 64 * FXS);
        const uint32_t WsA = smaddr(Wb + (ki & 1) * 32 * FWS);

        uint32_t a0[4], a1[4];
        ldsm4(a0[0], a0[1], a0[2], a0[3], XsA + (uint32_t)(wm * 16 * FXS + a_off) * 2);
        ldsm4(a1[0], a1[1], a1[2], a1[3], XsA + (uint32_t)(wm * 16 * FXS + a_off + 16) * 2);
#pragma unroll
        for (int nt = 0; nt < 24; nt++) {
            uint32_t r0, r1, r2, r3;
            ldsm4t(r0, r1, r2, r3, WsA + (uint32_t)(b_off + wn * 192 + nt * 8) * 2);
            uint32_t b01[2] = {r0, r1}, b23[2] = {r2, r3};
            mma16(acc[nt], a0, b01);
            mma16(acc[nt], a1, b23);
        }
        __syncthreads();
    }

    // epilogue: route each n-tile to Q/K/V; Q pre-scaled into log2 domain
    const float qsc = 0.088388347648318447f * 1.4426950408889634f;
    const int r = row0 + wm * 16 + g;
#pragma unroll
    for (int nt = 0; nt < 24; nt++) {
        const int ncol = wn * 192 + nt * 8 + 2 * tig;
        const int mat = ncol >> 7, col = ncol & 127;
        __half* Outh = (mat == 0) ? g_Qh : ((mat == 1) ? g_Kh : g_Vh);
        const float sc = (mat == 0) ? qsc : 1.0f;
        *(uint32_t*)(Outh + (size_t)r       * HDIM + col) = ph2(acc[nt][0] * sc, acc[nt][1] * sc);
        *(uint32_t*)(Outh + (size_t)(r + 8) * HDIM + col) = ph2(acc[nt][2] * sc, acc[nt][3] * sc);
    }
}

// ======================= flash attention (chunked split-K) =================
// grid (256, NB): bx -> qtile = 63-(bx>>2), chunk = bx&3.
// Each CTA handles kt in [chunk*16, min(chunk*16+16, qtile+1)) -- <=16 steps,
// bounding the makespan near the 18.7-steps/slot average. Empty chunks exit.
#define HS 136                       // half-stride per smem row (272 B)
#define ATT_SMEM (4 * 64 * HS * 2)   // 2 K bufs + 2 V bufs = 69632 B

__global__ __launch_bounds__(128, 3) void attn_kernel()
{
    extern __shared__ __half hsm[];
    __half* Kb = hsm;                  // [2][64*HS]
    __half* Vb = hsm + 2 * 64 * HS;    // [2][64*HS]

    const int tid  = threadIdx.x;
    const int warp = tid >> 5, lane = tid & 31;
    const int g = lane >> 2, tig = lane & 3;
    const int rb = warp * 16;
    const int b  = blockIdx.y;

    const int qtile = 63 - ((int)blockIdx.x >> 2);   // longest first
    const int chunk = (int)blockIdx.x & 3;
    const int n  = qtile + 1;
    const int kt0 = chunk * CHUNK;
    if (kt0 >= n) return;                            // empty chunk
    const int kt1 = (kt0 + CHUNK < n) ? kt0 + CHUNK : n;
    const int qbase = qtile * 64;

    const __half* Q = g_Qh + (size_t)b * SEQ * HDIM;
    const __half* K = g_Kh + (size_t)b * SEQ * HDIM;
    const __half* V = g_Vh + (size_t)b * SEQ * HDIM;

    auto issue_stage = [&](int kbase, int s) {
        __half* Kd = Kb + s * 64 * HS;
        __half* Vd = Vb + s * 64 * HS;
#pragma unroll
        for (int c = tid; c < 1024; c += 128) {
            int r = c >> 4, c8 = c & 15;
            cp16(smaddr(Kd + r * HS + c8 * 8),
                 K + (size_t)(kbase + r) * HDIM + c8 * 8);
            cp16(smaddr(Vd + r * HS + c8 * 8),
                 V + (size_t)(kbase + r) * HDIM + c8 * 8);
        }
        cp_commit();
    };

    float o[16][4];
#pragma unroll
    for (int nt = 0; nt < 16; nt++)
#pragma unroll
        for (int j = 0; j < 4; j++) o[nt][j] = 0.f;
    float mr[2] = {-INFINITY, -INFINITY};
    float lr[2] = {0.f, 0.f};

    {
        // Q -> register A-fragments (fp16, log2-prescaled in gmem)
        uint32_t qa[8][4];
#pragma unroll
        for (int ks = 0; ks < 8; ks++) {
            const __half* q0 = Q + (size_t)(qbase + rb + g)     * HDIM + ks * 16;
            const __half* q1 = Q + (size_t)(qbase + rb + g + 8) * HDIM + ks * 16;
            qa[ks][0] = *(const uint32_t*)(q0 + 2 * tig);
            qa[ks][1] = *(const uint32_t*)(q1 + 2 * tig);
            qa[ks][2] = *(const uint32_t*)(q0 + 2 * tig + 8);
            qa[ks][3] = *(const uint32_t*)(q1 + 2 * tig + 8);
        }

        // ldmatrix per-thread offsets (in halves)
        const int kq_off = (lane & 7) * HS + (lane >> 3) * 8;
        const int vv_off = lane * HS;

        // prologue: 2-deep prefetch
        issue_stage(kt0 * 64, kt0 & 1);
        if (kt0 + 1 < kt1) issue_stage((kt0 + 1) * 64, (kt0 + 1) & 1);
        else               cp_commit();

        for (int kt = kt0; kt < kt1; kt++) {
            cp_wait<1>();          // stage kt arrived
            __syncthreads();

            const uint32_t KsA = smaddr(Kb + (kt & 1) * 64 * HS);
            const uint32_t VsA = smaddr(Vb + (kt & 1) * 64 * HS);

            // -------- S = Q K^T  (16x64 per warp; log2-domain scores) --------
            float s[8][4];
#pragma unroll
            for (int ni = 0; ni < 8; ni++)
#pragma unroll
                for (int j = 0; j < 4; j++) s[ni][j] = 0.f;

#pragma unroll
            for (int ni = 0; ni < 8; ni++) {
                const uint32_t base = KsA + (uint32_t)(ni * 8 * HS + kq_off) * 2;
#pragma unroll
                for (int kc = 0; kc < 4; kc++) {
                    uint32_t r0, r1, r2, r3;
                    ldsm4(r0, r1, r2, r3, base + kc * 64);
                    uint32_t b01[2] = {r0, r1}, b23[2] = {r2, r3};
                    mma16(s[ni], qa[2 * kc],     b01);
                    mma16(s[ni], qa[2 * kc + 1], b23);
                }
            }

            // -------- causal mask (diagonal tile only) --------
            if (kt == qtile) {
                const int r0l = rb + g, r1l = rb + g + 8;
#pragma unroll
                for (int ni = 0; ni < 8; ni++) {
                    const int c = ni * 8 + 2 * tig;
                    s[ni][0] = (c     <= r0l) ? s[ni][0] : -INFINITY;
                    s[ni][1] = (c + 1 <= r0l) ? s[ni][1] : -INFINITY;
                    s[ni][2] = (c     <= r1l) ? s[ni][2] : -INFINITY;
                    s[ni][3] = (c + 1 <= r1l) ? s[ni][3] : -INFINITY;
                }
            }

            // -------- online softmax (log2 domain, single EX2 per element) ----
#pragma unroll
            for (int h = 0; h < 2; h++) {
                float tm = -INFINITY;
#pragma unroll
                for (int ni = 0; ni < 8; ni++)
                    tm = fmaxf(tm, fmaxf(s[ni][2 * h], s[ni][2 * h + 1]));
                tm = fmaxf(tm, __shfl_xor_sync(0xffffffffu, tm, 1));
                tm = fmaxf(tm, __shfl_xor_sync(0xffffffffu, tm, 2));

                const float mn = fmaxf(mr[h], tm);
                const float alpha = ex2(mr[h] - mn);
                mr[h] = mn;

                float rs = 0.f;
#pragma unroll
                for (int ni = 0; ni < 8; ni++) {
                    float p0 = ex2(s[ni][2 * h]     - mn);
                    float p1 = ex2(s[ni][2 * h + 1] - mn);
                    s[ni][2 * h] = p0; s[ni][2 * h + 1] = p1;
                    rs += p0 + p1;
                }
                rs += __shfl_xor_sync(0xffffffffu, rs, 1);
                rs += __shfl_xor_sync(0xffffffffu, rs, 2);
                lr[h] = lr[h] * alpha + rs;

#pragma unroll
                for (int nt = 0; nt < 16; nt++) {
                    o[nt][2 * h]     *= alpha;
                    o[nt][2 * h + 1] *= alpha;
                }
            }

            // -------- P -> fp16 A-fragments --------
            uint32_t pa[4][4];
#pragma unroll
            for (int js = 0; js < 4; js++) {
                pa[js][0] = ph2(s[2 * js][0],     s[2 * js][1]);
                pa[js][1] = ph2(s[2 * js][2],     s[2 * js][3]);
                pa[js][2] = ph2(s[2 * js + 1][0], s[2 * js + 1][1]);
                pa[js][3] = ph2(s[2 * js + 1][2], s[2 * js + 1][3]);
            }

            // -------- O += P V  (16x128 per warp) --------
#pragma unroll
            for (int nt = 0; nt < 16; nt++) {
                const uint32_t base = VsA + (uint32_t)(vv_off + nt * 8) * 2;
#pragma unroll
                for (int kc = 0; kc < 2; kc++) {
                    uint32_t r0, r1, r2, r3;
                    ldsm4t(r0, r1, r2, r3, base + kc * (32 * HS * 2));
                    uint32_t b01[2] = {r0, r1}, b23[2] = {r2, r3};
                    mma16(o[nt], pa[2 * kc],     b01);
                    mma16(o[nt], pa[2 * kc + 1], b23);
                }
            }

            // -------- all warps done reading stage kt; refill its buffer ------
            __syncthreads();
            if (kt + 2 < kt1) issue_stage((kt + 2) * 64, kt & 1);
            else              cp_commit();    // keep wait<1> invariant exact
        }

        cp_wait<0>();
    }

    // -------- epilogue: write partial (o, m, l); m in log2 domain --------
    const size_t pidx = ((size_t)(b * NQT + qtile) * NCH + chunk);
    float* Po = g_Po + pidx * (64 * HDIM);
#pragma unroll
    for (int nt = 0; nt < 16; nt++) {
        const int c = nt * 8 + 2 * tig;
        *(float2*)(Po + (rb + g)     * HDIM + c) = make_float2(o[nt][0], o[nt][1]);
        *(float2*)(Po + (rb + g + 8) * HDIM + c) = make_float2(o[nt][2], o[nt][3]);
    }
    if (tig == 0) {
        g_Pm[pidx * 64 + rb + g]     = mr[0];
        g_Pm[pidx * 64 + rb + g + 8] = mr[1];
        g_Pl[pidx * 64 + rb + g]     = lr[0];
        g_Pl[pidx * 64 + rb + g + 8] = lr[1];
    }
}

// ======================= split-K merge =========================
// grid (NQT*8, NB), 256 threads; each block merges an 8-row slab of one qtile,
// combining its nch = ceil((q+1)/CHUNK) chunk partials.
__global__ __launch_bounds__(256) void merge_kernel(float* __restrict__ Out)
{
    const int q = blockIdx.x >> 3, oct = blockIdx.x & 7, b = blockIdx.y;
    const int nch = (q + CHUNK) / CHUNK;      // ceil((q+1)/CHUNK)
    const size_t base = (size_t)(b * NQT + q) * NCH;

    const int t = threadIdx.x;
    const int r  = oct * 8 + (t >> 5);    // 8 rows per block, 32 thr/row
    const int c0 = (t & 31) * 4;          // one float4 per thread

    float m[NCH], l[NCH];
    float M = -INFINITY;
#pragma unroll
    for (int ch = 0; ch < NCH; ch++) {
        if (ch < nch) {
            m[ch] = g_Pm[(base + ch) * 64 + r];
            l[ch] = g_Pl[(base + ch) * 64 + r];
            M = fmaxf(M, m[ch]);
        }
    }
    float L = 0.f, w[NCH];
#pragma unroll
    for (int ch = 0; ch < NCH; ch++) {
        if (ch < nch) {
            w[ch] = ex2(m[ch] - M);
            L += l[ch] * w[ch];
        }
    }
    const float invL = 1.0f / L;

    float4 res = make_float4(0.f, 0.f, 0.f, 0.f);
#pragma unroll
    for (int ch = 0; ch < NCH; ch++) {
        if (ch < nch) {
            const float* Po = g_Po + (base + ch) * (64 * HDIM);
            float4 a = *(const float4*)(Po + r * HDIM + c0);
            const float W = w[ch];
            res.x += a.x * W; res.y += a.y * W;
            res.z += a.z * W; res.w += a.w * W;
        }
    }
    res.x *= invL; res.y *= invL; res.z *= invL; res.w *= invL;

    float* O = Out + (size_t)b * SEQ * HDIM + (size_t)(q * 64 + r) * HDIM;
    *(float4*)(O + c0) = res;
}

// =========================== launch =============================
extern "C" void kernel_launch(void* const* d_in, const int* in_sizes, int n_in,
                              void* d_out, int out_size)
{
    (void)in_sizes; (void)n_in; (void)out_size;
    const float* X  = (const float*)d_in[0];
    const float* Wq = (const float*)d_in[1];
    const float* Wk = (const float*)d_in[2];
    const float* Wv = (const float*)d_in[3];
    float* Out = (float*)d_out;

    static int attr_set = 0;
    if (!attr_set) {
        cudaFuncSetAttribute(fused_proj_kernel,
                             cudaFuncAttributeMaxDynamicSharedMemorySize,
                             FUSED_SMEM);
        cudaFuncSetAttribute(attn_kernel,
                             cudaFuncAttributeMaxDynamicSharedMemorySize,
                             ATT_SMEM);
        attr_set = 1;
    }

    // W fp32 -> fp16 (concat layout)
    dim3 wgrid(DDIM * HDIM / (256 * 8), 3);
    convert_W_kernel<<<wgrid, 256>>>(Wq, Wk, Wv);

    // Fused QKV projection (reads fp32 X once; one wave at 2 CTAs/SM)
    fused_proj_kernel<<<BSTOT / 64, 256, FUSED_SMEM>>>(X);

    // Flash attention, chunked split-K (<=16 steps per CTA)
    dim3 agrid(NQT * NCH, NB);
    attn_kernel<<<agrid, 128, ATT_SMEM>>>();

    // Merge chunk partials (8 blocks per qtile)
    dim3 mgrid(NQT * 8, NB);
    merge_kernel<<<mgrid, 256>>>(Out);
}

// round 17
// speedup vs baseline: 1.1041x; 1.0047x over previous
#include <cuda_runtime.h>
#include <cuda_fp16.h>
#include <math.h>
#include <stdint.h>

// Problem shape (fixed by the dataset)
#define NB      4
#define SEQ     4096
#define DDIM    1024
#define HDIM    128
#define BSTOT   (NB * SEQ)          // 16384 rows
#define NQT     64                  // q-tiles per batch (SEQ/64)
#define NCH     4                   // max KV chunks per qtile
#define CHUNK   16                  // tile-steps per chunk

// ---------------- scratch (no cudaMalloc allowed) ----------------
__device__ __half g_Wh[3 * DDIM * HDIM];    // fp16 Wq|Wk|Wv
__device__ __half g_Qh[BSTOT * HDIM];       // fp16 Q (pre-scaled by log2e/sqrt(128))
__device__ __half g_Kh[BSTOT * HDIM];
__device__ __half g_Vh[BSTOT * HDIM];
// split-K partials: [b][qtile][chunk]{ o:64x128, m:64, l:64 }  (m in log2 domain)
__device__ float g_Po[NB * NQT * NCH * 64 * HDIM];
__device__ float g_Pm[NB * NQT * NCH * 64];
__device__ float g_Pl[NB * NQT * NCH * 64];

// ------------------- helpers -------------------
// fp16: D += A(16x16, row) * B(16x8, col), fp32 accum
__device__ __forceinline__ void mma16(float* c, const uint32_t* a, const uint32_t* b) {
    asm volatile("mma.sync.aligned.m16n8k16.row.col.f32.f16.f16.f32 "
        "{%0,%1,%2,%3}, {%4,%5,%6,%7}, {%8,%9}, {%0,%1,%2,%3};"
        : "+f"(c[0]), "+f"(c[1]), "+f"(c[2]), "+f"(c[3])
        : "r"(a[0]), "r"(a[1]), "r"(a[2]), "r"(a[3]), "r"(b[0]), "r"(b[1]));
}
__device__ __forceinline__ void ldsm4(uint32_t& r0, uint32_t& r1, uint32_t& r2, uint32_t& r3,
                                      uint32_t addr) {
    asm volatile("ldmatrix.sync.aligned.m8n8.x4.shared.b16 {%0,%1,%2,%3}, [%4];"
        : "=r"(r0), "=r"(r1), "=r"(r2), "=r"(r3) : "r"(addr));
}
__device__ __forceinline__ void ldsm4t(uint32_t& r0, uint32_t& r1, uint32_t& r2, uint32_t& r3,
                                       uint32_t addr) {
    asm volatile("ldmatrix.sync.aligned.m8n8.x4.trans.shared.b16 {%0,%1,%2,%3}, [%4];"
        : "=r"(r0), "=r"(r1), "=r"(r2), "=r"(r3) : "r"(addr));
}
// pack two f32 -> f16x2 (lo = first element)
__device__ __forceinline__ uint32_t ph2(float lo, float hi) {
    uint32_t r; asm("cvt.rn.f16x2.f32 %0, %1, %2;" : "=r"(r) : "f"(hi), "f"(lo)); return r;
}
// 2^x, single MUFU op (exp done in log2 domain)
__device__ __forceinline__ float ex2(float x) {
    float r; asm("ex2.approx.ftz.f32 %0, %1;" : "=f"(r) : "f"(x)); return r;
}
__device__ __forceinline__ uint32_t smaddr(const void* p) {
    return (uint32_t)__cvta_generic_to_shared(p);
}
__device__ __forceinline__ void cp16(uint32_t s, const void* g) {
    asm volatile("cp.async.ca.shared.global [%0], [%1], 16;" :: "r"(s), "l"(g));
}
__device__ __forceinline__ void cp_commit() {
    asm volatile("cp.async.commit_group;");
}
template <int N>
__device__ __forceinline__ void cp_wait() {
    asm volatile("cp.async.wait_group %0;" :: "n"(N));
}

// ======================= W fp32 -> fp16 =========================
__global__ __launch_bounds__(256) void convert_W_kernel(
    const float* __restrict__ Wq, const float* __restrict__ Wk,
    const float* __restrict__ Wv)
{
    const float* W = (blockIdx.y == 0) ? Wq : ((blockIdx.y == 1) ? Wk : Wv);
    size_t i = ((size_t)blockIdx.x * 256 + threadIdx.x) * 8;
    float4 a = *(const float4*)(W + i);
    float4 b = *(const float4*)(W + i + 4);
    uint4 o;
    o.x = ph2(a.x, a.y); o.y = ph2(a.z, a.w);
    o.z = ph2(b.x, b.y); o.w = ph2(b.z, b.w);
    *(uint4*)(g_Wh + (size_t)blockIdx.y * DDIM * HDIM + i) = o;
}

// ======================= fused QKV projection =========================
// [Q|K|V][64 rows, 384 cols] = X[64,1024] (fp32, converted in-kernel) @ Wh[1024,384].
// 256 thr = 8 warps: wm=warp&3 (16 rows), wn=warp>>2 (192 cols = 24 n-tiles).
#define FXS 40    // X fp16 smem stride (halves)
#define FWS 392   // W fp16 smem stride (halves)
#define FUSED_SMEM ((2 * 64 * FXS + 2 * 32 * FWS) * 2)   // 60416 B

__global__ __launch_bounds__(256, 2) void fused_proj_kernel(const float* __restrict__ X)
{
    extern __shared__ __half fsm[];
    __half* Xb = fsm;                    // [2][64*FXS]
    __half* Wb = fsm + 2 * 64 * FXS;     // [2][32*FWS]

    const int tid  = threadIdx.x;
    const int warp = tid >> 5, lane = tid & 31;
    const int g = lane >> 2, tig = lane & 3;
    const int wm = warp & 3;      // 4 M-groups x 16 rows
    const int wn = warp >> 2;     // 2 N-groups x 192 cols
    const int row0 = blockIdx.x * 64;

    auto issue_W = [&](int k0, int s) {
        __half* Wd = Wb + s * 32 * FWS;
#pragma unroll
        for (int c = tid; c < 1536; c += 256) {     // 32 rows x 48 chunks of 8 halves
            int r = c / 48, cc = c % 48;
            int mat = cc >> 4, col = (cc & 15) * 8;
            cp16(smaddr(Wd + r * FWS + cc * 8),
                 g_Wh + (size_t)mat * DDIM * HDIM + (size_t)(k0 + r) * HDIM + col);
        }
        cp_commit();
    };

    // X staging: two float4 per thread per stage (64 rows x 32 cols)
    const int xr = tid >> 2;              // 64 rows, 4 threads per row
    const int xc0 = (tid & 3) * 4;        // cols xc0 and xc0+16

    float acc[24][4];
#pragma unroll
    for (int nt = 0; nt < 24; nt++)
#pragma unroll
        for (int j = 0; j < 4; j++) acc[nt][j] = 0.f;

    float4 xreg0 = *(const float4*)(X + (size_t)(row0 + xr) * DDIM + xc0);
    float4 xreg1 = *(const float4*)(X + (size_t)(row0 + xr) * DDIM + xc0 + 16);
    issue_W(0, 0);

    const int a_off = (lane & 15) * FXS + (lane >> 4) * 8;
    const int b_off = lane * FWS;

    for (int ki = 0; ki < 32; ki++) {
        {   // store prefetched X tile (cvt fp32->fp16) into buf ki&1
            __half* Xd = Xb + (ki & 1) * 64 * FXS + xr * FXS;
            uint2 p0; p0.x = ph2(xreg0.x, xreg0.y); p0.y = ph2(xreg0.z, xreg0.w);
            uint2 p1; p1.x = ph2(xreg1.x, xreg1.y); p1.y = ph2(xreg1.z, xreg1.w);
            *(uint2*)(Xd + xc0)      = p0;
            *(uint2*)(Xd + xc0 + 16) = p1;
        }
        if (ki < 31) {
            const float* Xr = X + (size_t)(row0 + xr) * DDIM + (ki + 1) * 32;
            xreg0 = *(const float4*)(Xr + xc0);
            xreg1 = *(const float4*)(Xr + xc0 + 16);
            issue_W((ki + 1) * 32, (ki + 1) & 1);
            cp_wait<1>();
        } else {
            cp_wait<0>();
        }
        __syncthreads();

        const uint32_t XsA = smaddr(Xb + (ki & 1) * 64 * FXS);
        const uint32_t WsA = smaddr(Wb + (ki & 1) * 32 * FWS);

        uint32_t a0[4], a1[4];
        ldsm4(a0[0], a0[1], a0[2], a0[3], XsA + (uint32_t)(wm * 16 * FXS + a_off) * 2);
        ldsm4(a1[0], a1[1], a1[2], a1[3], XsA + (uint32_t)(wm * 16 * FXS + a_off + 16) * 2);
#pragma unroll
        for (int nt = 0; nt < 24; nt++) {
            uint32_t r0, r1, r2, r3;
            ldsm4t(r0, r1, r2, r3, WsA + (uint32_t)(b_off + wn * 192 + nt * 8) * 2);
            uint32_t b01[2] = {r0, r1}, b23[2] = {r2, r3};
            mma16(acc[nt], a0, b01);
            mma16(acc[nt], a1, b23);
        }
        __syncthreads();
    }

    // epilogue: route each n-tile to Q/K/V; Q pre-scaled into log2 domain
    const float qsc = 0.088388347648318447f * 1.4426950408889634f;
    const int r = row0 + wm * 16 + g;
#pragma unroll
    for (int nt = 0; nt < 24; nt++) {
        const int ncol = wn * 192 + nt * 8 + 2 * tig;
        const int mat = ncol >> 7, col = ncol & 127;
        __half* Outh = (mat == 0) ? g_Qh : ((mat == 1) ? g_Kh : g_Vh);
        const float sc = (mat == 0) ? qsc : 1.0f;
        *(uint32_t*)(Outh + (size_t)r       * HDIM + col) = ph2(acc[nt][0] * sc, acc[nt][1] * sc);
        *(uint32_t*)(Outh + (size_t)(r + 8) * HDIM + col) = ph2(acc[nt][2] * sc, acc[nt][3] * sc);
    }
}

// ======================= flash attention (chunked split-K) =================
// grid (256, NB): bx -> qtile = 63-(bx>>2), chunk = bx&3.
// Each CTA handles kt in [chunk*16, min(chunk*16+16, qtile+1)) -- <=16 steps,
// bounding the makespan near the 18.7-steps/slot average. Empty chunks exit.
#define HS 136                       // half-stride per smem row (272 B)
#define ATT_SMEM (4 * 64 * HS * 2)   // 2 K bufs + 2 V bufs = 69632 B

__global__ __launch_bounds__(128, 3) void attn_kernel()
{
    extern __shared__ __half hsm[];
    __half* Kb = hsm;                  // [2][64*HS]
    __half* Vb = hsm + 2 * 64 * HS;    // [2][64*HS]

    const int tid  = threadIdx.x;
    const int warp = tid >> 5, lane = tid & 31;
    const int g = lane >> 2, tig = lane & 3;
    const int rb = warp * 16;
    const int b  = blockIdx.y;

    const int qtile = 63 - ((int)blockIdx.x >> 2);   // longest first
    const int chunk = (int)blockIdx.x & 3;
    const int n  = qtile + 1;
    const int kt0 = chunk * CHUNK;
    if (kt0 >= n) return;                            // empty chunk
    const int kt1 = (kt0 + CHUNK < n) ? kt0 + CHUNK : n;
    const int qbase = qtile * 64;

    const __half* Q = g_Qh + (size_t)b * SEQ * HDIM;
    const __half* K = g_Kh + (size_t)b * SEQ * HDIM;
    const __half* V = g_Vh + (size_t)b * SEQ * HDIM;

    auto issue_stage = [&](int kbase, int s) {
        __half* Kd = Kb + s * 64 * HS;
        __half* Vd = Vb + s * 64 * HS;
#pragma unroll
        for (int c = tid; c < 1024; c += 128) {
            int r = c >> 4, c8 = c & 15;
            cp16(smaddr(Kd + r * HS + c8 * 8),
                 K + (size_t)(kbase + r) * HDIM + c8 * 8);
            cp16(smaddr(Vd + r * HS + c8 * 8),
                 V + (size_t)(kbase + r) * HDIM + c8 * 8);
        }
        cp_commit();
    };

    float o[16][4];
#pragma unroll
    for (int nt = 0; nt < 16; nt++)
#pragma unroll
        for (int j = 0; j < 4; j++) o[nt][j] = 0.f;
    float mr[2] = {-INFINITY, -INFINITY};
    float lr[2] = {0.f, 0.f};

    {
        // Q -> register A-fragments (fp16, log2-prescaled in gmem)
        uint32_t qa[8][4];
#pragma unroll
        for (int ks = 0; ks < 8; ks++) {
            const __half* q0 = Q + (size_t)(qbase + rb + g)     * HDIM + ks * 16;
            const __half* q1 = Q + (size_t)(qbase + rb + g + 8) * HDIM + ks * 16;
            qa[ks][0] = *(const uint32_t*)(q0 + 2 * tig);
            qa[ks][1] = *(const uint32_t*)(q1 + 2 * tig);
            qa[ks][2] = *(const uint32_t*)(q0 + 2 * tig + 8);
            qa[ks][3] = *(const uint32_t*)(q1 + 2 * tig + 8);
        }

        // ldmatrix per-thread offsets (in halves)
        const int kq_off = (lane & 7) * HS + (lane >> 3) * 8;
        const int vv_off = lane * HS;

        // prologue: 2-deep prefetch
        issue_stage(kt0 * 64, kt0 & 1);
        if (kt0 + 1 < kt1) issue_stage((kt0 + 1) * 64, (kt0 + 1) & 1);
        else               cp_commit();

        for (int kt = kt0; kt < kt1; kt++) {
            cp_wait<1>();          // stage kt arrived
            __syncthreads();

            const uint32_t KsA = smaddr(Kb + (kt & 1) * 64 * HS);
            const uint32_t VsA = smaddr(Vb + (kt & 1) * 64 * HS);

            // -------- S = Q K^T  (16x64 per warp; log2-domain scores) --------
            float s[8][4];
#pragma unroll
            for (int ni = 0; ni < 8; ni++)
#pragma unroll
                for (int j = 0; j < 4; j++) s[ni][j] = 0.f;

#pragma unroll
            for (int ni = 0; ni < 8; ni++) {
                const uint32_t base = KsA + (uint32_t)(ni * 8 * HS + kq_off) * 2;
#pragma unroll
                for (int kc = 0; kc < 4; kc++) {
                    uint32_t r0, r1, r2, r3;
                    ldsm4(r0, r1, r2, r3, base + kc * 64);
                    uint32_t b01[2] = {r0, r1}, b23[2] = {r2, r3};
                    mma16(s[ni], qa[2 * kc],     b01);
                    mma16(s[ni], qa[2 * kc + 1], b23);
                }
            }

            // -------- causal mask (diagonal tile only) --------
            if (kt == qtile) {
                const int r0l = rb + g, r1l = rb + g + 8;
#pragma unroll
                for (int ni = 0; ni < 8; ni++) {
                    const int c = ni * 8 + 2 * tig;
                    s[ni][0] = (c     <= r0l) ? s[ni][0] : -INFINITY;
                    s[ni][1] = (c + 1 <= r0l) ? s[ni][1] : -INFINITY;
                    s[ni][2] = (c     <= r1l) ? s[ni][2] : -INFINITY;
                    s[ni][3] = (c + 1 <= r1l) ? s[ni][3] : -INFINITY;
                }
            }

            // -------- online softmax (log2 domain, single EX2 per element) ----
#pragma unroll
            for (int h = 0; h < 2; h++) {
                float tm = -INFINITY;
#pragma unroll
                for (int ni = 0; ni < 8; ni++)
                    tm = fmaxf(tm, fmaxf(s[ni][2 * h], s[ni][2 * h + 1]));
                tm = fmaxf(tm, __shfl_xor_sync(0xffffffffu, tm, 1));
                tm = fmaxf(tm, __shfl_xor_sync(0xffffffffu, tm, 2));

                const float mn = fmaxf(mr[h], tm);
                const float alpha = ex2(mr[h] - mn);
                mr[h] = mn;

                float rs = 0.f;
#pragma unroll
                for (int ni = 0; ni < 8; ni++) {
                    float p0 = ex2(s[ni][2 * h]     - mn);
                    float p1 = ex2(s[ni][2 * h + 1] - mn);
                    s[ni][2 * h] = p0; s[ni][2 * h + 1] = p1;
                    rs += p0 + p1;
                }
                rs += __shfl_xor_sync(0xffffffffu, rs, 1);
                rs += __shfl_xor_sync(0xffffffffu, rs, 2);
                lr[h] = lr[h] * alpha + rs;

#pragma unroll
                for (int nt = 0; nt < 16; nt++) {
                    o[nt][2 * h]     *= alpha;
                    o[nt][2 * h + 1] *= alpha;
                }
            }

            // -------- P -> fp16 A-fragments --------
            uint32_t pa[4][4];
#pragma unroll
            for (int js = 0; js < 4; js++) {
                pa[js][0] = ph2(s[2 * js][0],     s[2 * js][1]);
                pa[js][1] = ph2(s[2 * js][2],     s[2 * js][3]);
                pa[js][2] = ph2(s[2 * js + 1][0], s[2 * js + 1][1]);
                pa[js][3] = ph2(s[2 * js + 1][2], s[2 * js + 1][3]);
            }

            // -------- O += P V  (16x128 per warp) --------
#pragma unroll
            for (int nt = 0; nt < 16; nt++) {
                const uint32_t base = VsA + (uint32_t)(vv_off + nt * 8) * 2;
#pragma unroll
                for (int kc = 0; kc < 2; kc++) {
                    uint32_t r0, r1, r2, r3;
                    ldsm4t(r0, r1, r2, r3, base + kc * (32 * HS * 2));
                    uint32_t b01[2] = {r0, r1}, b23[2] = {r2, r3};
                    mma16(o[nt], pa[2 * kc],     b01);
                    mma16(o[nt], pa[2 * kc + 1], b23);
                }
            }

            // -------- all warps done reading stage kt; refill its buffer ------
            __syncthreads();
            if (kt + 2 < kt1) issue_stage((kt + 2) * 64, kt & 1);
            else              cp_commit();    // keep wait<1> invariant exact
        }

        cp_wait<0>();
    }

    // -------- epilogue: write partial (o, m, l); m in log2 domain --------
    const size_t pidx = ((size_t)(b * NQT + qtile) * NCH + chunk);
    float* Po = g_Po + pidx * (64 * HDIM);
#pragma unroll
    for (int nt = 0; nt < 16; nt++) {
        const int c = nt * 8 + 2 * tig;
        *(float2*)(Po + (rb + g)     * HDIM + c) = make_float2(o[nt][0], o[nt][1]);
        *(float2*)(Po + (rb + g + 8) * HDIM + c) = make_float2(o[nt][2], o[nt][3]);
    }
    if (tig == 0) {
        g_Pm[pidx * 64 + rb + g]     = mr[0];
        g_Pm[pidx * 64 + rb + g + 8] = mr[1];
        g_Pl[pidx * 64 + rb + g]     = lr[0];
        g_Pl[pidx * 64 + rb + g + 8] = lr[1];
    }
}

// ======================= split-K merge =========================
// grid (NQT*8, NB), 256 threads; each block merges an 8-row slab of one qtile,
// combining its nch = ceil((q+1)/CHUNK) chunk partials.
__global__ __launch_bounds__(256) void merge_kernel(float* __restrict__ Out)
{
    const int q = blockIdx.x >> 3, oct = blockIdx.x & 7, b = blockIdx.y;
    const int nch = (q + CHUNK) / CHUNK;      // ceil((q+1)/CHUNK)
    const size_t base = (size_t)(b * NQT + q) * NCH;

    const int t = threadIdx.x;
    const int r  = oct * 8 + (t >> 5);    // 8 rows per block, 32 thr/row
    const int c0 = (t & 31) * 4;          // one float4 per thread

    float m[NCH], l[NCH];
    float M = -INFINITY;
#pragma unroll
    for (int ch = 0; ch < NCH; ch++) {
        if (ch < nch) {
            m[ch] = g_Pm[(base + ch) * 64 + r];
            l[ch] = g_Pl[(base + ch) * 64 + r];
            M = fmaxf(M, m[ch]);
        }
    }
    float L = 0.f, w[NCH];
#pragma unroll
    for (int ch = 0; ch < NCH; ch++) {
        if (ch < nch) {
            w[ch] = ex2(m[ch] - M);
            L += l[ch] * w[ch];
        }
    }
    const float invL = 1.0f / L;

    float4 res = make_float4(0.f, 0.f, 0.f, 0.f);
#pragma unroll
    for (int ch = 0; ch < NCH; ch++) {
        if (ch < nch) {
            const float* Po = g_Po + (base + ch) * (64 * HDIM);
            float4 a = *(const float4*)(Po + r * HDIM + c0);
            const float W = w[ch];
            res.x += a.x * W; res.y += a.y * W;
            res.z += a.z * W; res.w += a.w * W;
        }
    }
    res.x *= invL; res.y *= invL; res.z *= invL; res.w *= invL;

    float* O = Out + (size_t)b * SEQ * HDIM + (size_t)(q * 64 + r) * HDIM;
    *(float4*)(O + c0) = res;
}

// =========================== launch =============================
extern "C" void kernel_launch(void* const* d_in, const int* in_sizes, int n_in,
                              void* d_out, int out_size)
{
    (void)in_sizes; (void)n_in; (void)out_size;
    const float* X  = (const float*)d_in[0];
    const float* Wq = (const float*)d_in[1];
    const float* Wk = (const float*)d_in[2];
    const float* Wv = (const float*)d_in[3];
    float* Out = (float*)d_out;

    static int attr_set = 0;
    if (!attr_set) {
        cudaFuncSetAttribute(fused_proj_kernel,
                             cudaFuncAttributeMaxDynamicSharedMemorySize,
                             FUSED_SMEM);
        cudaFuncSetAttribute(attn_kernel,
                             cudaFuncAttributeMaxDynamicSharedMemorySize,
                             ATT_SMEM);
        attr_set = 1;
    }

    // W fp32 -> fp16 (concat layout)
    dim3 wgrid(DDIM * HDIM / (256 * 8), 3);
    convert_W_kernel<<<wgrid, 256>>>(Wq, Wk, Wv);

    // Fused QKV projection (reads fp32 X once; one wave at 2 CTAs/SM)
    fused_proj_kernel<<<BSTOT / 64, 256, FUSED_SMEM>>>(X);

    // Flash attention, chunked split-K (<=16 steps per CTA)
    dim3 agrid(NQT * NCH, NB);
    attn_kernel<<<agrid, 128, ATT_SMEM>>>();

    // Merge chunk partials (8 blocks per qtile)
    dim3 mgrid(NQT * 8, NB);
    merge_kernel<<<mgrid, 256>>>(Out);
}